// round 11
// baseline (speedup 1.0000x reference)
#include <cuda_runtime.h>
#include <cuda_fp16.h>

// Problem constants (fixed for this dataset)
#define BB   4
#define CC   128
#define HH   128
#define WW   128
#define GG   4
#define PP   9       // K*K taps
#define NOFF 72      // G*P*2
#define NMSK 36      // G*P
#define TILE 32      // pixels per block
#define NTHR 256
#define ROW  36      // xsT row length in floats (32 px + 4 pad, 16B-aligned)
#define SP   132     // padded scratch dim (img+pad); entry (b,g,yp,xp)
#define NPIX (BB * HH * WW)
#define NBLK (NPIX / TILE)          // 2048

// fp16 pair-gather scratch: entry (b,g,yp,xp) = 128B =
//   [64B: ch0-31 of img col (xp-1), row (yp-1)] [64B: ch0-31 of img col xp]
// zero outside the image. 278784 entries * 128B = 35.7 MB.
#define NENT (BB * GG * SP * SP)
__device__ uint4 xh_scratch[NENT * 8];

// per-(pixel, g*9+p) mask-folded bilinear corner weights + scratch entry index
__device__ float4 gswt[NPIX * NMSK];    // 37.7 MB
__device__ int    gsent[NPIX * NMSK];   //  9.4 MB

// =======================================================================
// Kernel A: fp16 scratch conversion + offset/mask projection + weights
// FMA-bound; conversion loop hides under the matvec FMA stream.
// =======================================================================
__global__ __launch_bounds__(NTHR, 5) void dcnv3_proj(
    const float* __restrict__ in,     // (B,H,W,C) channel-last
    const float* __restrict__ Woff,   // (C, 72) row-major
    const float* __restrict__ boff,   // (72)
    const float* __restrict__ Wmask,  // (C, 36) row-major
    const float* __restrict__ bmask)  // (36)
{
    __shared__ __align__(16) float xsT[CC * ROW];     // 18 KB
    __shared__ float offs[TILE][NOFF];                // 9 KB
    __shared__ float msk[TILE][NMSK];                 // 4.5 KB

    const int tid = threadIdx.x;
    const int blk = blockIdx.x;

    // ---- conv part: fp32 (B,H,W,C) -> fp16 pair scratch (grid-strided) ----
    for (int t = blk * NTHR + tid; t < NENT * 8; t += NBLK * NTHR) {
        const int part = t & 7;          // 16B slice within the 128B entry
        const int e    = t >> 3;
        const int xp = e % SP;
        const int yp = (e / SP) % SP;
        const int g  = (e / (SP * SP)) % GG;
        const int bb = e / (SP * SP * GG);
        const int col = xp - 1 + (part >> 2);   // part<4: left col, else right
        const int row = yp - 1;
        const int ch0 = (part & 3) * 8;
        uint4 v = make_uint4(0u, 0u, 0u, 0u);
        if ((unsigned)row < (unsigned)HH && (unsigned)col < (unsigned)WW) {
            const float4* s = reinterpret_cast<const float4*>(
                in + (((size_t)bb * HH + row) * WW + col) * CC + g * 32 + ch0);
            const float4 f0 = s[0];
            const float4 f1 = s[1];
            __half2 h0 = __floats2half2_rn(f0.x, f0.y);
            __half2 h1 = __floats2half2_rn(f0.z, f0.w);
            __half2 h2 = __floats2half2_rn(f1.x, f1.y);
            __half2 h3 = __floats2half2_rn(f1.z, f1.w);
            v.x = *reinterpret_cast<unsigned int*>(&h0);
            v.y = *reinterpret_cast<unsigned int*>(&h1);
            v.z = *reinterpret_cast<unsigned int*>(&h2);
            v.w = *reinterpret_cast<unsigned int*>(&h3);
        }
        xh_scratch[t] = v;
    }

    const int wt = blk % (WW / TILE);
    const int h  = (blk / (WW / TILE)) % HH;
    const int b  = blk / ((WW / TILE) * HH);
    const int w0 = wt * TILE;

    // ---- phase 0: load 32 pixels' features TRANSPOSED into xsT ----
    const float4* xbase4 = reinterpret_cast<const float4*>(
        in + (((size_t)b * HH + h) * WW + w0) * CC);
    const int r = tid & 3;
    #pragma unroll
    for (int it = 0; it < 4; it++) {
        const int i  = tid + it * NTHR;      // 0..1023
        const int q  = i >> 7;               // pixel quad 0..7
        const int k4 = (i >> 2) & 31;        // channel quad 0..31
        float4 v = xbase4[(q * 4 + r) * (CC / 4) + k4];
        float a0 = v.x, a1 = v.y, a2 = v.z, a3 = v.w;
        {
            float s0 = (r & 1) ? a0 : a1;
            float s1 = (r & 1) ? a2 : a3;
            float g0 = __shfl_xor_sync(0xFFFFFFFF, s0, 1);
            float g1 = __shfl_xor_sync(0xFFFFFFFF, s1, 1);
            if (r & 1) { a0 = g0; a2 = g1; } else { a1 = g0; a3 = g1; }
        }
        {
            float u0 = (r & 2) ? a0 : a2;
            float u1 = (r & 2) ? a1 : a3;
            float h0 = __shfl_xor_sync(0xFFFFFFFF, u0, 2);
            float h1 = __shfl_xor_sync(0xFFFFFFFF, u1, 2);
            if (r & 2) { a0 = h0; a1 = h1; } else { a2 = h0; a3 = h1; }
        }
        *reinterpret_cast<float4*>(&xsT[(4 * k4 + r) * ROW + 4 * q]) =
            make_float4(a0, a1, a2, a3);
    }
    __syncthreads();

    // ---- phase 1: register-tiled matvec, 4 pixels x 4 outputs / thread ----
    if (tid < 216) {
        const int jq = tid >> 3;             // 0..26
        const int pg = tid & 7;              // 0..7
        const int p0 = pg * 4;
        const bool is_off = (jq < 18);
        const int j0 = is_off ? jq * 4 : (jq - 18) * 4;
        const float* Wb = (is_off ? Woff : Wmask) + j0;
        const int ws = is_off ? NOFF : NMSK;
        const float* bias = is_off ? boff : bmask;

        float4 acc0 = make_float4(0.f, 0.f, 0.f, 0.f);
        float4 acc1 = make_float4(0.f, 0.f, 0.f, 0.f);
        float4 acc2 = make_float4(0.f, 0.f, 0.f, 0.f);
        float4 acc3 = make_float4(0.f, 0.f, 0.f, 0.f);

        #pragma unroll 4
        for (int k = 0; k < CC; k++) {
            const float4 xq = *reinterpret_cast<const float4*>(&xsT[k * ROW + p0]);
            const float4 w  = *reinterpret_cast<const float4*>(&Wb[k * ws]);
            acc0.x = fmaf(xq.x, w.x, acc0.x);
            acc0.y = fmaf(xq.x, w.y, acc0.y);
            acc0.z = fmaf(xq.x, w.z, acc0.z);
            acc0.w = fmaf(xq.x, w.w, acc0.w);
            acc1.x = fmaf(xq.y, w.x, acc1.x);
            acc1.y = fmaf(xq.y, w.y, acc1.y);
            acc1.z = fmaf(xq.y, w.z, acc1.z);
            acc1.w = fmaf(xq.y, w.w, acc1.w);
            acc2.x = fmaf(xq.z, w.x, acc2.x);
            acc2.y = fmaf(xq.z, w.y, acc2.y);
            acc2.z = fmaf(xq.z, w.z, acc2.z);
            acc2.w = fmaf(xq.z, w.w, acc2.w);
            acc3.x = fmaf(xq.w, w.x, acc3.x);
            acc3.y = fmaf(xq.w, w.y, acc3.y);
            acc3.z = fmaf(xq.w, w.z, acc3.z);
            acc3.w = fmaf(xq.w, w.w, acc3.w);
        }
        const float4 bv = *reinterpret_cast<const float4*>(bias + j0);
        acc0.x += bv.x; acc0.y += bv.y; acc0.z += bv.z; acc0.w += bv.w;
        acc1.x += bv.x; acc1.y += bv.y; acc1.z += bv.z; acc1.w += bv.w;
        acc2.x += bv.x; acc2.y += bv.y; acc2.z += bv.z; acc2.w += bv.w;
        acc3.x += bv.x; acc3.y += bv.y; acc3.z += bv.z; acc3.w += bv.w;

        if (is_off) {
            *reinterpret_cast<float4*>(&offs[p0 + 0][j0]) = acc0;
            *reinterpret_cast<float4*>(&offs[p0 + 1][j0]) = acc1;
            *reinterpret_cast<float4*>(&offs[p0 + 2][j0]) = acc2;
            *reinterpret_cast<float4*>(&offs[p0 + 3][j0]) = acc3;
        } else {
            *reinterpret_cast<float4*>(&msk[p0 + 0][j0]) = acc0;
            *reinterpret_cast<float4*>(&msk[p0 + 1][j0]) = acc1;
            *reinterpret_cast<float4*>(&msk[p0 + 2][j0]) = acc2;
            *reinterpret_cast<float4*>(&msk[p0 + 3][j0]) = acc3;
        }
    }
    __syncthreads();

    // ---- phase 2: softmax over the 9 taps per (pixel, group) ----
    if (tid < TILE * GG) {
        const int pp = tid / GG, g = tid % GG;
        float* m = &msk[pp][g * PP];
        float mx = m[0];
        #pragma unroll
        for (int p = 1; p < PP; p++) mx = fmaxf(mx, m[p]);
        float e[PP], s = 0.f;
        #pragma unroll
        for (int p = 0; p < PP; p++) { e[p] = __expf(m[p] - mx); s += e[p]; }
        const float inv = 1.f / s;
        #pragma unroll
        for (int p = 0; p < PP; p++) m[p] = e[p] * inv;
    }
    __syncthreads();

    // ---- phase 2.5: mask-folded corner weights + entry -> GLOBAL ----
    for (int idx = tid; idx < TILE * NMSK; idx += NTHR) {
        const int pp = idx / NMSK;
        const int gp = idx % NMSK;
        const int g  = gp / PP;
        const int p  = gp % PP;
        const float dx = offs[pp][gp * 2 + 0];
        const float dy = offs[pp][gp * 2 + 1];
        const float px = (float)(w0 + pp) + (float)(p / 3) + dx;   // padded coords
        const float py = (float)h + (float)(p % 3) + dy;
        const float x0f = floorf(px), y0f = floorf(py);
        const float tx = px - x0f, ty = py - y0f;
        const int ix0 = (int)x0f, iy0 = (int)y0f;
        const float m = msk[pp][gp];

        float w00 = (1.f - tx) * (1.f - ty) * m;
        float w10 = tx * (1.f - ty) * m;
        float w01 = (1.f - tx) * ty * m;
        float w11 = tx * ty * m;
        const bool vx0 = ((unsigned)(ix0 - 1) < (unsigned)WW);
        const bool vx1 = ((unsigned)(ix0)     < (unsigned)WW);
        const bool vy0 = ((unsigned)(iy0 - 1) < (unsigned)HH);
        const bool vy1 = ((unsigned)(iy0)     < (unsigned)HH);
        if (!(vx0 && vy0)) w00 = 0.f;
        if (!(vx1 && vy0)) w10 = 0.f;
        if (!(vx0 && vy1)) w01 = 0.f;
        if (!(vx1 && vy1)) w11 = 0.f;

        const int pix = ((b * HH + h) * WW + w0 + pp);
        gswt[pix * NMSK + gp] = make_float4(w00, w10, w01, w11);
        const bool ok = ((unsigned)ix0 <= 130u) && ((unsigned)iy0 <= 130u);
        gsent[pix * NMSK + gp] = ok ? (((b * GG + g) * SP + iy0) * SP + ix0) : 0;
    }
}

// =======================================================================
// Kernel B: pure fp16 pair gather. No smem, no barriers; deep occupancy.
// =======================================================================
__global__ __launch_bounds__(NTHR, 6) void dcnv3_gather(
    float* __restrict__ out)          // (B,H,W,C) channel-last
{
    const int tid = threadIdx.x;
    const int blk = blockIdx.x;
    const int wt = blk % (WW / TILE);
    const int h  = (blk / (WW / TILE)) % HH;
    const int b  = blk / ((WW / TILE) * HH);
    const int w0 = wt * TILE;

    const int lane = tid & 31;
    const int g3   = lane >> 3;         // group 0..3
    const int sub  = lane & 7;          // 16B slice of 128B entry
    const int cr   = sub >> 2;          // 0: left corner col, 1: right

    #pragma unroll
    for (int pass = 0; pass < 4; pass++) {
        const int pp  = (tid >> 5) + pass * 8;
        const int pix = ((b * HH + h) * WW + w0 + pp);
        const float4* wbase = &gswt[(size_t)pix * NMSK + g3 * PP];
        const int*    ebase = &gsent[(size_t)pix * NMSK + g3 * PP];

        float acc[8];
        #pragma unroll
        for (int i = 0; i < 8; i++) acc[i] = 0.f;

        #pragma unroll
        for (int p = 0; p < PP; p++) {
            const float4 wv = wbase[p];         // broadcast LDG.128 (L2-hot)
            const int e = ebase[p];
            const float wr0 = cr ? wv.y : wv.x; // row y0 weight for this column
            const float wr1 = cr ? wv.w : wv.z; // row y1 weight
            const uint4 d0 = xh_scratch[e * 8 + sub];
            const uint4 d1 = xh_scratch[(e + SP) * 8 + sub];
            float2 f;
            f = __half22float2(*reinterpret_cast<const __half2*>(&d0.x));
            acc[0] = fmaf(wr0, f.x, acc[0]); acc[1] = fmaf(wr0, f.y, acc[1]);
            f = __half22float2(*reinterpret_cast<const __half2*>(&d0.y));
            acc[2] = fmaf(wr0, f.x, acc[2]); acc[3] = fmaf(wr0, f.y, acc[3]);
            f = __half22float2(*reinterpret_cast<const __half2*>(&d0.z));
            acc[4] = fmaf(wr0, f.x, acc[4]); acc[5] = fmaf(wr0, f.y, acc[5]);
            f = __half22float2(*reinterpret_cast<const __half2*>(&d0.w));
            acc[6] = fmaf(wr0, f.x, acc[6]); acc[7] = fmaf(wr0, f.y, acc[7]);
            f = __half22float2(*reinterpret_cast<const __half2*>(&d1.x));
            acc[0] = fmaf(wr1, f.x, acc[0]); acc[1] = fmaf(wr1, f.y, acc[1]);
            f = __half22float2(*reinterpret_cast<const __half2*>(&d1.y));
            acc[2] = fmaf(wr1, f.x, acc[2]); acc[3] = fmaf(wr1, f.y, acc[3]);
            f = __half22float2(*reinterpret_cast<const __half2*>(&d1.z));
            acc[4] = fmaf(wr1, f.x, acc[4]); acc[5] = fmaf(wr1, f.y, acc[5]);
            f = __half22float2(*reinterpret_cast<const __half2*>(&d1.w));
            acc[6] = fmaf(wr1, f.x, acc[6]); acc[7] = fmaf(wr1, f.y, acc[7]);
        }
        // combine left/right corner partials (lane ^ 4)
        #pragma unroll
        for (int i = 0; i < 8; i++)
            acc[i] += __shfl_xor_sync(0xFFFFFFFF, acc[i], 4);

        if (!(lane & 4)) {      // sub in 0..3 -> channel octet
            float* op = out + (size_t)pix * CC + g3 * 32 + sub * 8;
            *reinterpret_cast<float4*>(op) =
                make_float4(acc[0], acc[1], acc[2], acc[3]);
            *reinterpret_cast<float4*>(op + 4) =
                make_float4(acc[4], acc[5], acc[6], acc[7]);
        }
    }
}

extern "C" void kernel_launch(void* const* d_in, const int* in_sizes, int n_in,
                              void* d_out, int out_size) {
    const float* inp   = (const float*)d_in[0];
    const float* Woff  = (const float*)d_in[1];
    const float* boff  = (const float*)d_in[2];
    const float* Wmask = (const float*)d_in[3];
    const float* bmask = (const float*)d_in[4];
    float* out = (float*)d_out;

    dcnv3_proj<<<NBLK, NTHR>>>(inp, Woff, boff, Wmask, bmask);
    dcnv3_gather<<<NBLK, NTHR>>>(out);
}

// round 12
// speedup vs baseline: 1.2761x; 1.2761x over previous
#include <cuda_runtime.h>
#include <cuda_fp16.h>

// Problem constants (fixed for this dataset)
#define BB   4
#define CC   128
#define HH   128
#define WW   128
#define GG   4
#define PP   9       // K*K taps
#define NOFF 72      // G*P*2
#define NMSK 36      // G*P
#define TILE 32      // pixels per block
#define NTHR 256
#define ROW  36      // xsT row length in floats (32 px + 4 pad, 16B-aligned)
#define SP   132     // padded scratch dim (img+pad); entry (b,g,yp,xp)
#define SP8  (SP * 8)  // row step in uint4 units

// fp16 pair-gather scratch: entry (b,g,yp,xp) = 128B =
//   [64B: ch0-31 of img col (xp-1), row (yp-1)] [64B: ch0-31 of img col xp]
// zero outside the image. 278784 entries * 128B = 35.7 MB.
#define NENT (BB * GG * SP * SP)
__device__ uint4 xh_scratch[NENT * 8];

// overlay buffer: phases 0/1 use it as xsT[CC][ROW] (18432 B);
// phases 2.5/3 use it as swt[TILE][NMSK] float4 (18432 B) + sent[TILE][NMSK] int
#define UBUF_BYTES (TILE * NMSK * 16 + TILE * NMSK * 4)   // 23040

// ---------------- conversion kernel: fp32 (B,H,W,C) -> fp16 pair scratch ----
__global__ __launch_bounds__(256) void conv_fp16(const float* __restrict__ in) {
    const int t = blockIdx.x * 256 + threadIdx.x;
    if (t >= NENT * 8) return;
    const int part = t & 7;          // 16B slice within the 128B entry
    const int e    = t >> 3;
    const int xp = e % SP;
    const int yp = (e / SP) % SP;
    const int g  = (e / (SP * SP)) % GG;
    const int b  =  e / (SP * SP * GG);
    const int col = xp - 1 + (part >> 2);   // part<4: left col, part>=4: right
    const int row = yp - 1;
    const int ch0 = (part & 3) * 8;
    uint4 v = make_uint4(0u, 0u, 0u, 0u);
    if ((unsigned)row < (unsigned)HH && (unsigned)col < (unsigned)WW) {
        const float4* s = reinterpret_cast<const float4*>(
            in + (((size_t)b * HH + row) * WW + col) * CC + g * 32 + ch0);
        const float4 f0 = s[0];
        const float4 f1 = s[1];
        __half2 h0 = __floats2half2_rn(f0.x, f0.y);
        __half2 h1 = __floats2half2_rn(f0.z, f0.w);
        __half2 h2 = __floats2half2_rn(f1.x, f1.y);
        __half2 h3 = __floats2half2_rn(f1.z, f1.w);
        v.x = *reinterpret_cast<unsigned int*>(&h0);
        v.y = *reinterpret_cast<unsigned int*>(&h1);
        v.z = *reinterpret_cast<unsigned int*>(&h2);
        v.w = *reinterpret_cast<unsigned int*>(&h3);
    }
    xh_scratch[t] = v;
}

// ---------------- main fused kernel ----------------------------------------
__global__ __launch_bounds__(NTHR, 5) void dcnv3_fused(
    const float* __restrict__ in,     // (B,H,W,C) channel-last
    const float* __restrict__ Woff,   // (C, 72) row-major
    const float* __restrict__ boff,   // (72)
    const float* __restrict__ Wmask,  // (C, 36) row-major
    const float* __restrict__ bmask,  // (36)
    float* __restrict__ out)          // (B,H,W,C) channel-last
{
    __shared__ __align__(16) char ubuf[UBUF_BYTES];   // 22.5 KB (xsT | swt+sent)
    __shared__ float offs[TILE][NOFF];                // 9 KB
    __shared__ float msk[TILE][NMSK];                 // 4.5 KB

    float* xsT           = reinterpret_cast<float*>(ubuf);             // [CC][ROW]
    float4 (*swt)[NMSK]  = reinterpret_cast<float4(*)[NMSK]>(ubuf);
    int (*sent)[NMSK]    = reinterpret_cast<int(*)[NMSK]>(ubuf + TILE * NMSK * 16);

    const int tid = threadIdx.x;
    const int blk = blockIdx.x;
    const int wt = blk % (WW / TILE);
    const int h  = (blk / (WW / TILE)) % HH;
    const int b  = blk / ((WW / TILE) * HH);
    const int w0 = wt * TILE;

    // ---- phase 0: load 32 pixels' features TRANSPOSED into xsT (fp32) ----
    const float4* xbase4 = reinterpret_cast<const float4*>(
        in + (((size_t)b * HH + h) * WW + w0) * CC);
    const int r = tid & 3;
    #pragma unroll
    for (int it = 0; it < 4; it++) {
        const int i  = tid + it * NTHR;      // 0..1023
        const int q  = i >> 7;               // pixel quad 0..7
        const int k4 = (i >> 2) & 31;        // channel quad 0..31
        float4 v = xbase4[(q * 4 + r) * (CC / 4) + k4];
        float a0 = v.x, a1 = v.y, a2 = v.z, a3 = v.w;
        {
            float s0 = (r & 1) ? a0 : a1;
            float s1 = (r & 1) ? a2 : a3;
            float g0 = __shfl_xor_sync(0xFFFFFFFF, s0, 1);
            float g1 = __shfl_xor_sync(0xFFFFFFFF, s1, 1);
            if (r & 1) { a0 = g0; a2 = g1; } else { a1 = g0; a3 = g1; }
        }
        {
            float u0 = (r & 2) ? a0 : a2;
            float u1 = (r & 2) ? a1 : a3;
            float h0 = __shfl_xor_sync(0xFFFFFFFF, u0, 2);
            float h1 = __shfl_xor_sync(0xFFFFFFFF, u1, 2);
            if (r & 2) { a0 = h0; a1 = h1; } else { a2 = h0; a3 = h1; }
        }
        *reinterpret_cast<float4*>(&xsT[(4 * k4 + r) * ROW + 4 * q]) =
            make_float4(a0, a1, a2, a3);
    }
    __syncthreads();

    // ---- phase 1: register-tiled matvec (fp32, proven best) ----
    if (tid < 216) {
        const int jq = tid >> 3;             // 0..26
        const int pg = tid & 7;              // 0..7
        const int p0 = pg * 4;
        const bool is_off = (jq < 18);
        const int j0 = is_off ? jq * 4 : (jq - 18) * 4;
        const float* Wb = (is_off ? Woff : Wmask) + j0;
        const int ws = is_off ? NOFF : NMSK;
        const float* bias = is_off ? boff : bmask;

        float4 acc0 = make_float4(0.f, 0.f, 0.f, 0.f);
        float4 acc1 = make_float4(0.f, 0.f, 0.f, 0.f);
        float4 acc2 = make_float4(0.f, 0.f, 0.f, 0.f);
        float4 acc3 = make_float4(0.f, 0.f, 0.f, 0.f);

        #pragma unroll 4
        for (int k = 0; k < CC; k++) {
            const float4 xq = *reinterpret_cast<const float4*>(&xsT[k * ROW + p0]);
            const float4 w  = *reinterpret_cast<const float4*>(&Wb[k * ws]);
            acc0.x = fmaf(xq.x, w.x, acc0.x);
            acc0.y = fmaf(xq.x, w.y, acc0.y);
            acc0.z = fmaf(xq.x, w.z, acc0.z);
            acc0.w = fmaf(xq.x, w.w, acc0.w);
            acc1.x = fmaf(xq.y, w.x, acc1.x);
            acc1.y = fmaf(xq.y, w.y, acc1.y);
            acc1.z = fmaf(xq.y, w.z, acc1.z);
            acc1.w = fmaf(xq.y, w.w, acc1.w);
            acc2.x = fmaf(xq.z, w.x, acc2.x);
            acc2.y = fmaf(xq.z, w.y, acc2.y);
            acc2.z = fmaf(xq.z, w.z, acc2.z);
            acc2.w = fmaf(xq.z, w.w, acc2.w);
            acc3.x = fmaf(xq.w, w.x, acc3.x);
            acc3.y = fmaf(xq.w, w.y, acc3.y);
            acc3.z = fmaf(xq.w, w.z, acc3.z);
            acc3.w = fmaf(xq.w, w.w, acc3.w);
        }
        const float4 bv = *reinterpret_cast<const float4*>(bias + j0);
        acc0.x += bv.x; acc0.y += bv.y; acc0.z += bv.z; acc0.w += bv.w;
        acc1.x += bv.x; acc1.y += bv.y; acc1.z += bv.z; acc1.w += bv.w;
        acc2.x += bv.x; acc2.y += bv.y; acc2.z += bv.z; acc2.w += bv.w;
        acc3.x += bv.x; acc3.y += bv.y; acc3.z += bv.z; acc3.w += bv.w;

        if (is_off) {
            *reinterpret_cast<float4*>(&offs[p0 + 0][j0]) = acc0;
            *reinterpret_cast<float4*>(&offs[p0 + 1][j0]) = acc1;
            *reinterpret_cast<float4*>(&offs[p0 + 2][j0]) = acc2;
            *reinterpret_cast<float4*>(&offs[p0 + 3][j0]) = acc3;
        } else {
            *reinterpret_cast<float4*>(&msk[p0 + 0][j0]) = acc0;
            *reinterpret_cast<float4*>(&msk[p0 + 1][j0]) = acc1;
            *reinterpret_cast<float4*>(&msk[p0 + 2][j0]) = acc2;
            *reinterpret_cast<float4*>(&msk[p0 + 3][j0]) = acc3;
        }
    }
    __syncthreads();

    // ---- phase 2: softmax over the 9 taps per (pixel, group) ----
    if (tid < TILE * GG) {
        const int pp = tid / GG, g = tid % GG;
        float* m = &msk[pp][g * PP];
        float mx = m[0];
        #pragma unroll
        for (int p = 1; p < PP; p++) mx = fmaxf(mx, m[p]);
        float e[PP], s = 0.f;
        #pragma unroll
        for (int p = 0; p < PP; p++) { e[p] = __expf(m[p] - mx); s += e[p]; }
        const float inv = 1.f / s;
        #pragma unroll
        for (int p = 0; p < PP; p++) m[p] = e[p] * inv;
    }
    __syncthreads();

    // ---- phase 2.5: mask-folded corner weights + scratch entry (x8 units) ----
    for (int idx = tid; idx < TILE * NMSK; idx += NTHR) {
        const int pp = idx / NMSK;
        const int gp = idx % NMSK;
        const int g  = gp / PP;
        const int p  = gp % PP;
        const float dx = offs[pp][gp * 2 + 0];
        const float dy = offs[pp][gp * 2 + 1];
        const float px = (float)(w0 + pp) + (float)(p / 3) + dx;   // padded coords
        const float py = (float)h + (float)(p % 3) + dy;
        const float x0f = floorf(px), y0f = floorf(py);
        const float tx = px - x0f, ty = py - y0f;
        const int ix0 = (int)x0f, iy0 = (int)y0f;
        const float m = msk[pp][gp];

        float w00 = (1.f - tx) * (1.f - ty) * m;
        float w10 = tx * (1.f - ty) * m;
        float w01 = (1.f - tx) * ty * m;
        float w11 = tx * ty * m;
        const bool vx0 = ((unsigned)(ix0 - 1) < (unsigned)WW);
        const bool vx1 = ((unsigned)(ix0)     < (unsigned)WW);
        const bool vy0 = ((unsigned)(iy0 - 1) < (unsigned)HH);
        const bool vy1 = ((unsigned)(iy0)     < (unsigned)HH);
        if (!(vx0 && vy0)) w00 = 0.f;
        if (!(vx1 && vy0)) w10 = 0.f;
        if (!(vx0 && vy1)) w01 = 0.f;
        if (!(vx1 && vy1)) w11 = 0.f;

        swt[pp][gp] = make_float4(w00, w10, w01, w11);
        // scratch entry in uint4 units (pre-scaled by 8); row+1 = +SP8.
        // Clamp to 0 when outside padded array (weights all zero then).
        const bool ok = ((unsigned)ix0 <= 130u) && ((unsigned)iy0 <= 130u);
        sent[pp][gp] = ok ? ((((b * GG + g) * SP + iy0) * SP + ix0) * 8) : 0;
    }
    __syncthreads();

    // ---- phase 3: fp16 pair gather, depth-2 software pipelined.
    // warp = pixel; lane = (g, sub); sub>>2 = corner col half, sub&3 = ch octet.
    const int lane = tid & 31;
    const int g3   = lane >> 3;
    const int sub  = lane & 7;
    const int cr   = sub >> 2;          // 0: left corner col, 1: right
    const int gp0  = g3 * PP;

    #pragma unroll
    for (int pass = 0; pass < 4; pass++) {
        const int pp = (tid >> 5) + pass * 8;
        float acc[8];
        #pragma unroll
        for (int i = 0; i < 8; i++) acc[i] = 0.f;

        // prologue: tap 0's data loads
        int e0 = sent[pp][gp0];
        uint4 d0 = xh_scratch[e0 + sub];
        uint4 d1 = xh_scratch[e0 + SP8 + sub];

        #pragma unroll
        for (int p = 0; p < PP; p++) {
            uint4 n0, n1;
            if (p + 1 < PP) {                      // prefetch tap p+1
                const int en = sent[pp][gp0 + p + 1];
                n0 = xh_scratch[en + sub];
                n1 = xh_scratch[en + SP8 + sub];
            }
            const float4 wv = swt[pp][gp0 + p];
            const float wr0 = cr ? wv.y : wv.x;    // row y0 weight, this column
            const float wr1 = cr ? wv.w : wv.z;    // row y1 weight
            float2 f;
            f = __half22float2(*reinterpret_cast<const __half2*>(&d0.x));
            acc[0] = fmaf(wr0, f.x, acc[0]); acc[1] = fmaf(wr0, f.y, acc[1]);
            f = __half22float2(*reinterpret_cast<const __half2*>(&d0.y));
            acc[2] = fmaf(wr0, f.x, acc[2]); acc[3] = fmaf(wr0, f.y, acc[3]);
            f = __half22float2(*reinterpret_cast<const __half2*>(&d0.z));
            acc[4] = fmaf(wr0, f.x, acc[4]); acc[5] = fmaf(wr0, f.y, acc[5]);
            f = __half22float2(*reinterpret_cast<const __half2*>(&d0.w));
            acc[6] = fmaf(wr0, f.x, acc[6]); acc[7] = fmaf(wr0, f.y, acc[7]);
            f = __half22float2(*reinterpret_cast<const __half2*>(&d1.x));
            acc[0] = fmaf(wr1, f.x, acc[0]); acc[1] = fmaf(wr1, f.y, acc[1]);
            f = __half22float2(*reinterpret_cast<const __half2*>(&d1.y));
            acc[2] = fmaf(wr1, f.x, acc[2]); acc[3] = fmaf(wr1, f.y, acc[3]);
            f = __half22float2(*reinterpret_cast<const __half2*>(&d1.z));
            acc[4] = fmaf(wr1, f.x, acc[4]); acc[5] = fmaf(wr1, f.y, acc[5]);
            f = __half22float2(*reinterpret_cast<const __half2*>(&d1.w));
            acc[6] = fmaf(wr1, f.x, acc[6]); acc[7] = fmaf(wr1, f.y, acc[7]);
            d0 = n0; d1 = n1;
        }
        // combine left/right corner partials (lane ^ 4)
        #pragma unroll
        for (int i = 0; i < 8; i++)
            acc[i] += __shfl_xor_sync(0xFFFFFFFF, acc[i], 4);

        if (!(lane & 4)) {      // sub in 0..3 -> channel octet
            float* op = out + (((size_t)b * HH + h) * WW + (w0 + pp)) * CC
                            + g3 * 32 + sub * 8;
            *reinterpret_cast<float4*>(op) =
                make_float4(acc[0], acc[1], acc[2], acc[3]);
            *reinterpret_cast<float4*>(op + 4) =
                make_float4(acc[4], acc[5], acc[6], acc[7]);
        }
    }
}

extern "C" void kernel_launch(void* const* d_in, const int* in_sizes, int n_in,
                              void* d_out, int out_size) {
    const float* inp   = (const float*)d_in[0];
    const float* Woff  = (const float*)d_in[1];
    const float* boff  = (const float*)d_in[2];
    const float* Wmask = (const float*)d_in[3];
    const float* bmask = (const float*)d_in[4];
    float* out = (float*)d_out;

    const int conv_blocks = (NENT * 8 + 255) / 256;     // 8712
    conv_fp16<<<conv_blocks, 256>>>(inp);

    const int nblocks = BB * HH * (WW / TILE);          // 2048
    dcnv3_fused<<<nblocks, NTHR>>>(inp, Woff, boff, Wmask, bmask, out);
}

// round 13
// speedup vs baseline: 1.3173x; 1.0323x over previous
#include <cuda_runtime.h>
#include <cuda_fp16.h>

// Problem constants (fixed for this dataset)
#define BB   4
#define CC   128
#define HH   128
#define WW   128
#define GG   4
#define PP   9       // K*K taps
#define NOFF 72      // G*P*2
#define NMSK 36      // G*P
#define TILE 32      // pixels per block
#define NTHR 256
#define ROWH 40      // xsT_h row length in halves (32 px + 8 pad -> 80B rows)
#define SP   132     // padded scratch dim (img+pad); entry (b,g,yp,xp)
#define SP8  (SP * 8)  // row step in uint4 units

// fp16 pair-gather scratch: entry (b,g,yp,xp) = 128B =
//   [64B: ch0-31 of img col (xp-1), row (yp-1)] [64B: ch0-31 of img col xp]
// zero outside the image. 278784 entries * 128B = 35.7 MB.
#define NENT (BB * GG * SP * SP)
__device__ uint4 xh_scratch[NENT * 8];

// overlay buffer: phases 0/1 use it as xsT_h[CC][ROWH] fp16 (10240 B);
// phases 2.5/3 use it as swt[TILE][NMSK] float4 (18432 B) + sent[TILE][NMSK] int
#define UBUF_BYTES (TILE * NMSK * 16 + TILE * NMSK * 4)   // 23040

// ---------------- conversion kernel: fp32 (B,H,W,C) -> fp16 pair scratch ----
__global__ __launch_bounds__(256) void conv_fp16(const float* __restrict__ in) {
    const int t = blockIdx.x * 256 + threadIdx.x;
    if (t >= NENT * 8) return;
    const int part = t & 7;          // 16B slice within the 128B entry
    const int e    = t >> 3;
    const int xp = e % SP;
    const int yp = (e / SP) % SP;
    const int g  = (e / (SP * SP)) % GG;
    const int b  =  e / (SP * SP * GG);
    const int col = xp - 1 + (part >> 2);   // part<4: left col, part>=4: right
    const int row = yp - 1;
    const int ch0 = (part & 3) * 8;
    uint4 v = make_uint4(0u, 0u, 0u, 0u);
    if ((unsigned)row < (unsigned)HH && (unsigned)col < (unsigned)WW) {
        const float4* s = reinterpret_cast<const float4*>(
            in + (((size_t)b * HH + row) * WW + col) * CC + g * 32 + ch0);
        const float4 f0 = s[0];
        const float4 f1 = s[1];
        __half2 h0 = __floats2half2_rn(f0.x, f0.y);
        __half2 h1 = __floats2half2_rn(f0.z, f0.w);
        __half2 h2 = __floats2half2_rn(f1.x, f1.y);
        __half2 h3 = __floats2half2_rn(f1.z, f1.w);
        v.x = *reinterpret_cast<unsigned int*>(&h0);
        v.y = *reinterpret_cast<unsigned int*>(&h1);
        v.z = *reinterpret_cast<unsigned int*>(&h2);
        v.w = *reinterpret_cast<unsigned int*>(&h3);
    }
    xh_scratch[t] = v;
}

// ---------------- main fused kernel ----------------------------------------
__global__ __launch_bounds__(NTHR, 5) void dcnv3_fused(
    const float* __restrict__ in,     // (B,H,W,C) channel-last
    const float* __restrict__ Woff,   // (C, 72) row-major
    const float* __restrict__ boff,   // (72)
    const float* __restrict__ Wmask,  // (C, 36) row-major
    const float* __restrict__ bmask,  // (36)
    float* __restrict__ out)          // (B,H,W,C) channel-last
{
    __shared__ __align__(16) char ubuf[UBUF_BYTES];   // 22.5 KB
    __shared__ float offs[TILE][NOFF];                // 9 KB
    __shared__ float msk[TILE][NMSK];                 // 4.5 KB

    __half* xsT          = reinterpret_cast<__half*>(ubuf);            // [CC][ROWH]
    float4 (*swt)[NMSK]  = reinterpret_cast<float4(*)[NMSK]>(ubuf);
    int (*sent)[NMSK]    = reinterpret_cast<int(*)[NMSK]>(ubuf + TILE * NMSK * 16);

    const int tid = threadIdx.x;
    const int blk = blockIdx.x;
    const int wt = blk % (WW / TILE);
    const int h  = (blk / (WW / TILE)) % HH;
    const int b  = blk / ((WW / TILE) * HH);
    const int w0 = wt * TILE;

    // ---- phase 0: load 32 pixels' features TRANSPOSED into xsT as fp16 ----
    const float4* xbase4 = reinterpret_cast<const float4*>(
        in + (((size_t)b * HH + h) * WW + w0) * CC);
    const int r = tid & 3;
    #pragma unroll
    for (int it = 0; it < 4; it++) {
        const int i  = tid + it * NTHR;      // 0..1023
        const int q  = i >> 7;               // pixel quad 0..7
        const int k4 = (i >> 2) & 31;        // channel quad 0..31
        float4 v = xbase4[(q * 4 + r) * (CC / 4) + k4];
        float a0 = v.x, a1 = v.y, a2 = v.z, a3 = v.w;
        {
            float s0 = (r & 1) ? a0 : a1;
            float s1 = (r & 1) ? a2 : a3;
            float g0 = __shfl_xor_sync(0xFFFFFFFF, s0, 1);
            float g1 = __shfl_xor_sync(0xFFFFFFFF, s1, 1);
            if (r & 1) { a0 = g0; a2 = g1; } else { a1 = g0; a3 = g1; }
        }
        {
            float u0 = (r & 2) ? a0 : a2;
            float u1 = (r & 2) ? a1 : a3;
            float h0 = __shfl_xor_sync(0xFFFFFFFF, u0, 2);
            float h1 = __shfl_xor_sync(0xFFFFFFFF, u1, 2);
            if (r & 2) { a0 = h0; a1 = h1; } else { a2 = h0; a3 = h1; }
        }
        // lane holds channel (4*k4 + r) for pixels 4q..4q+3 -> fp16 pairs
        __half2 h01 = __floats2half2_rn(a0, a1);
        __half2 h23 = __floats2half2_rn(a2, a3);
        uint2 st;
        st.x = *reinterpret_cast<unsigned int*>(&h01);
        st.y = *reinterpret_cast<unsigned int*>(&h23);
        *reinterpret_cast<uint2*>(&xsT[(4 * k4 + r) * ROWH + 4 * q]) = st;
    }
    __syncthreads();

    // ---- phase 1: register-tiled matvec. 4 pixels x 4 outputs per thread.
    // x from fp16 shared (8B/thread/k -> 64B/warp, half the LDS wavefronts);
    // W LDG.128 broadcast; accumulation in fp32.
    if (tid < 216) {
        const int jq = tid >> 3;             // 0..26
        const int pg = tid & 7;              // 0..7
        const int p0 = pg * 4;
        const bool is_off = (jq < 18);
        const int j0 = is_off ? jq * 4 : (jq - 18) * 4;
        const float* Wb = (is_off ? Woff : Wmask) + j0;
        const int ws = is_off ? NOFF : NMSK;
        const float* bias = is_off ? boff : bmask;

        float4 acc0 = make_float4(0.f, 0.f, 0.f, 0.f);
        float4 acc1 = make_float4(0.f, 0.f, 0.f, 0.f);
        float4 acc2 = make_float4(0.f, 0.f, 0.f, 0.f);
        float4 acc3 = make_float4(0.f, 0.f, 0.f, 0.f);

        #pragma unroll 4
        for (int k = 0; k < CC; k++) {
            const uint2 xv = *reinterpret_cast<const uint2*>(&xsT[k * ROWH + p0]);
            const float2 f01 = __half22float2(*reinterpret_cast<const __half2*>(&xv.x));
            const float2 f23 = __half22float2(*reinterpret_cast<const __half2*>(&xv.y));
            const float4 w = *reinterpret_cast<const float4*>(&Wb[k * ws]);
            acc0.x = fmaf(f01.x, w.x, acc0.x);
            acc0.y = fmaf(f01.x, w.y, acc0.y);
            acc0.z = fmaf(f01.x, w.z, acc0.z);
            acc0.w = fmaf(f01.x, w.w, acc0.w);
            acc1.x = fmaf(f01.y, w.x, acc1.x);
            acc1.y = fmaf(f01.y, w.y, acc1.y);
            acc1.z = fmaf(f01.y, w.z, acc1.z);
            acc1.w = fmaf(f01.y, w.w, acc1.w);
            acc2.x = fmaf(f23.x, w.x, acc2.x);
            acc2.y = fmaf(f23.x, w.y, acc2.y);
            acc2.z = fmaf(f23.x, w.z, acc2.z);
            acc2.w = fmaf(f23.x, w.w, acc2.w);
            acc3.x = fmaf(f23.y, w.x, acc3.x);
            acc3.y = fmaf(f23.y, w.y, acc3.y);
            acc3.z = fmaf(f23.y, w.z, acc3.z);
            acc3.w = fmaf(f23.y, w.w, acc3.w);
        }
        const float4 bv = *reinterpret_cast<const float4*>(bias + j0);
        acc0.x += bv.x; acc0.y += bv.y; acc0.z += bv.z; acc0.w += bv.w;
        acc1.x += bv.x; acc1.y += bv.y; acc1.z += bv.z; acc1.w += bv.w;
        acc2.x += bv.x; acc2.y += bv.y; acc2.z += bv.z; acc2.w += bv.w;
        acc3.x += bv.x; acc3.y += bv.y; acc3.z += bv.z; acc3.w += bv.w;

        if (is_off) {
            *reinterpret_cast<float4*>(&offs[p0 + 0][j0]) = acc0;
            *reinterpret_cast<float4*>(&offs[p0 + 1][j0]) = acc1;
            *reinterpret_cast<float4*>(&offs[p0 + 2][j0]) = acc2;
            *reinterpret_cast<float4*>(&offs[p0 + 3][j0]) = acc3;
        } else {
            *reinterpret_cast<float4*>(&msk[p0 + 0][j0]) = acc0;
            *reinterpret_cast<float4*>(&msk[p0 + 1][j0]) = acc1;
            *reinterpret_cast<float4*>(&msk[p0 + 2][j0]) = acc2;
            *reinterpret_cast<float4*>(&msk[p0 + 3][j0]) = acc3;
        }
    }
    __syncthreads();

    // ---- phase 2: softmax over the 9 taps per (pixel, group) ----
    if (tid < TILE * GG) {
        const int pp = tid / GG, g = tid % GG;
        float* m = &msk[pp][g * PP];
        float mx = m[0];
        #pragma unroll
        for (int p = 1; p < PP; p++) mx = fmaxf(mx, m[p]);
        float e[PP], s = 0.f;
        #pragma unroll
        for (int p = 0; p < PP; p++) { e[p] = __expf(m[p] - mx); s += e[p]; }
        const float inv = 1.f / s;
        #pragma unroll
        for (int p = 0; p < PP; p++) m[p] = e[p] * inv;
    }
    __syncthreads();

    // ---- phase 2.5: mask-folded corner weights + scratch entry (x8 units) ----
    for (int idx = tid; idx < TILE * NMSK; idx += NTHR) {
        const int pp = idx / NMSK;
        const int gp = idx % NMSK;
        const int g  = gp / PP;
        const int p  = gp % PP;
        const float dx = offs[pp][gp * 2 + 0];
        const float dy = offs[pp][gp * 2 + 1];
        const float px = (float)(w0 + pp) + (float)(p / 3) + dx;   // padded coords
        const float py = (float)h + (float)(p % 3) + dy;
        const float x0f = floorf(px), y0f = floorf(py);
        const float tx = px - x0f, ty = py - y0f;
        const int ix0 = (int)x0f, iy0 = (int)y0f;
        const float m = msk[pp][gp];

        float w00 = (1.f - tx) * (1.f - ty) * m;
        float w10 = tx * (1.f - ty) * m;
        float w01 = (1.f - tx) * ty * m;
        float w11 = tx * ty * m;
        const bool vx0 = ((unsigned)(ix0 - 1) < (unsigned)WW);
        const bool vx1 = ((unsigned)(ix0)     < (unsigned)WW);
        const bool vy0 = ((unsigned)(iy0 - 1) < (unsigned)HH);
        const bool vy1 = ((unsigned)(iy0)     < (unsigned)HH);
        if (!(vx0 && vy0)) w00 = 0.f;
        if (!(vx1 && vy0)) w10 = 0.f;
        if (!(vx0 && vy1)) w01 = 0.f;
        if (!(vx1 && vy1)) w11 = 0.f;

        swt[pp][gp] = make_float4(w00, w10, w01, w11);
        // scratch entry in uint4 units (pre-scaled by 8); row+1 = +SP8.
        // Clamp to 0 when outside padded array (weights all zero then).
        const bool ok = ((unsigned)ix0 <= 130u) && ((unsigned)iy0 <= 130u);
        sent[pp][gp] = ok ? ((((b * GG + g) * SP + iy0) * SP + ix0) * 8) : 0;
    }
    __syncthreads();

    // ---- phase 3: fp16 pair gather.  warp = pixel; lane = (g, sub);
    // sub>>2 = corner col half, sub&3 = ch octet. ----
    const int lane = tid & 31;
    const int g3   = lane >> 3;
    const int sub  = lane & 7;
    const int cr   = sub >> 2;          // 0: left corner col, 1: right
    const int gp0  = g3 * PP;

    #pragma unroll
    for (int pass = 0; pass < 4; pass++) {
        const int pp = (tid >> 5) + pass * 8;
        float acc[8];
        #pragma unroll
        for (int i = 0; i < 8; i++) acc[i] = 0.f;

        #pragma unroll
        for (int p = 0; p < PP; p++) {
            const int gp = gp0 + p;
            const float4 wv = swt[pp][gp];
            const float wr0 = cr ? wv.y : wv.x;    // row y0 weight, this column
            const float wr1 = cr ? wv.w : wv.z;    // row y1 weight
            const int e = sent[pp][gp];
            const uint4 d0 = xh_scratch[e + sub];
            const uint4 d1 = xh_scratch[e + SP8 + sub];
            float2 f;
            f = __half22float2(*reinterpret_cast<const __half2*>(&d0.x));
            acc[0] = fmaf(wr0, f.x, acc[0]); acc[1] = fmaf(wr0, f.y, acc[1]);
            f = __half22float2(*reinterpret_cast<const __half2*>(&d0.y));
            acc[2] = fmaf(wr0, f.x, acc[2]); acc[3] = fmaf(wr0, f.y, acc[3]);
            f = __half22float2(*reinterpret_cast<const __half2*>(&d0.z));
            acc[4] = fmaf(wr0, f.x, acc[4]); acc[5] = fmaf(wr0, f.y, acc[5]);
            f = __half22float2(*reinterpret_cast<const __half2*>(&d0.w));
            acc[6] = fmaf(wr0, f.x, acc[6]); acc[7] = fmaf(wr0, f.y, acc[7]);
            f = __half22float2(*reinterpret_cast<const __half2*>(&d1.x));
            acc[0] = fmaf(wr1, f.x, acc[0]); acc[1] = fmaf(wr1, f.y, acc[1]);
            f = __half22float2(*reinterpret_cast<const __half2*>(&d1.y));
            acc[2] = fmaf(wr1, f.x, acc[2]); acc[3] = fmaf(wr1, f.y, acc[3]);
            f = __half22float2(*reinterpret_cast<const __half2*>(&d1.z));
            acc[4] = fmaf(wr1, f.x, acc[4]); acc[5] = fmaf(wr1, f.y, acc[5]);
            f = __half22float2(*reinterpret_cast<const __half2*>(&d1.w));
            acc[6] = fmaf(wr1, f.x, acc[6]); acc[7] = fmaf(wr1, f.y, acc[7]);
        }
        // combine left/right corner partials (lane ^ 4)
        #pragma unroll
        for (int i = 0; i < 8; i++)
            acc[i] += __shfl_xor_sync(0xFFFFFFFF, acc[i], 4);

        if (!(lane & 4)) {      // sub in 0..3 -> channel octet
            float* op = out + (((size_t)b * HH + h) * WW + (w0 + pp)) * CC
                            + g3 * 32 + sub * 8;
            *reinterpret_cast<float4*>(op) =
                make_float4(acc[0], acc[1], acc[2], acc[3]);
            *reinterpret_cast<float4*>(op + 4) =
                make_float4(acc[4], acc[5], acc[6], acc[7]);
        }
    }
}

extern "C" void kernel_launch(void* const* d_in, const int* in_sizes, int n_in,
                              void* d_out, int out_size) {
    const float* inp   = (const float*)d_in[0];
    const float* Woff  = (const float*)d_in[1];
    const float* boff  = (const float*)d_in[2];
    const float* Wmask = (const float*)d_in[3];
    const float* bmask = (const float*)d_in[4];
    float* out = (float*)d_out;

    const int conv_blocks = (NENT * 8 + 255) / 256;     // 8712
    conv_fp16<<<conv_blocks, 256>>>(inp);

    const int nblocks = BB * HH * (WW / TILE);          // 2048
    dcnv3_fused<<<nblocks, NTHR>>>(inp, Woff, boff, Wmask, bmask, out);
}

// round 14
// speedup vs baseline: 2.0402x; 1.5488x over previous
#include <cuda_runtime.h>
#include <cuda_fp16.h>

// Problem constants (fixed for this dataset)
#define BB   4
#define CC   128
#define HH   128
#define WW   128
#define GG   4
#define PP   9       // K*K taps
#define NOFF 72      // G*P*2
#define NMSK 36      // G*P
#define NJ   112     // padded outputs (14 n-tiles of 8): 72 off + 36 msk + 4 pad
#define NT_TILES 14
#define TILE 32      // pixels per block
#define NTHR 256
#define ROWA 136     // xh row length in halves (128 + 8 pad; 272B rows, conflict-free ldmatrix)
#define SP   132     // padded scratch dim (img+pad); entry (b,g,yp,xp)
#define SP8  (SP * 8)  // row step in uint4 units

// fp16 pair-gather scratch: entry (b,g,yp,xp) = 128B =
//   [64B: ch0-31 of img col (xp-1), row (yp-1)] [64B: ch0-31 of img col xp]
#define NENT (BB * GG * SP * SP)
__device__ uint4 xh_scratch[NENT * 8];

// fragment-ordered fp16 W for mma.m16n8k16 B operand:
// wfragB[(nt*8 + kt)*32 + lane] = {half2(W[k0][j],W[k0+1][j]), half2(W[k0+8][j],W[k0+9][j])}
// with k0 = kt*16 + (lane%4)*2, j = nt*8 + lane/4.  28672 B, L1-resident.
#define NFRAG (NT_TILES * 8 * 32)
__device__ uint2 wfragB[NFRAG];

// overlay buffer: phases 0/1 use it as xh[TILE][ROWA] fp16 (8704 B);
// phases 2.5/3 use it as swt[TILE][NMSK] float4 + sent[TILE][NMSK] int
#define UBUF_BYTES (TILE * NMSK * 16 + TILE * NMSK * 4)   // 23040

// ---------------- conversion kernel: fp32 (B,H,W,C) -> fp16 pair scratch ----
__global__ __launch_bounds__(256) void conv_fp16(const float* __restrict__ in) {
    const int t = blockIdx.x * 256 + threadIdx.x;
    if (t >= NENT * 8) return;
    const int part = t & 7;
    const int e    = t >> 3;
    const int xp = e % SP;
    const int yp = (e / SP) % SP;
    const int g  = (e / (SP * SP)) % GG;
    const int b  =  e / (SP * SP * GG);
    const int col = xp - 1 + (part >> 2);
    const int row = yp - 1;
    const int ch0 = (part & 3) * 8;
    uint4 v = make_uint4(0u, 0u, 0u, 0u);
    if ((unsigned)row < (unsigned)HH && (unsigned)col < (unsigned)WW) {
        const float4* s = reinterpret_cast<const float4*>(
            in + (((size_t)b * HH + row) * WW + col) * CC + g * 32 + ch0);
        const float4 f0 = s[0];
        const float4 f1 = s[1];
        __half2 h0 = __floats2half2_rn(f0.x, f0.y);
        __half2 h1 = __floats2half2_rn(f0.z, f0.w);
        __half2 h2 = __floats2half2_rn(f1.x, f1.y);
        __half2 h3 = __floats2half2_rn(f1.z, f1.w);
        v.x = *reinterpret_cast<unsigned int*>(&h0);
        v.y = *reinterpret_cast<unsigned int*>(&h1);
        v.z = *reinterpret_cast<unsigned int*>(&h2);
        v.w = *reinterpret_cast<unsigned int*>(&h3);
    }
    xh_scratch[t] = v;
}

// ---------------- W fragment builder ----------------
__device__ __forceinline__ float wall_get(const float* Woff, const float* Wmask,
                                          int k, int j) {
    if (j < NOFF) return Woff[k * NOFF + j];
    if (j < NOFF + NMSK) return Wmask[k * NMSK + (j - NOFF)];
    return 0.f;
}
__global__ __launch_bounds__(256) void build_wfrag(
    const float* __restrict__ Woff, const float* __restrict__ Wmask) {
    const int t = blockIdx.x * 256 + threadIdx.x;
    if (t >= NFRAG) return;
    const int lane = t & 31;
    const int kt   = (t >> 5) & 7;
    const int nt   = t >> 8;
    const int j  = nt * 8 + (lane >> 2);
    const int k0 = kt * 16 + (lane & 3) * 2;
    __half2 r0 = __floats2half2_rn(wall_get(Woff, Wmask, k0,     j),
                                   wall_get(Woff, Wmask, k0 + 1, j));
    __half2 r1 = __floats2half2_rn(wall_get(Woff, Wmask, k0 + 8, j),
                                   wall_get(Woff, Wmask, k0 + 9, j));
    uint2 v;
    v.x = *reinterpret_cast<unsigned int*>(&r0);
    v.y = *reinterpret_cast<unsigned int*>(&r1);
    wfragB[t] = v;
}

// ---------------- main fused kernel ----------------------------------------
__global__ __launch_bounds__(NTHR, 5) void dcnv3_fused(
    const float* __restrict__ in,     // (B,H,W,C) channel-last
    const float* __restrict__ boff,   // (72)
    const float* __restrict__ bmask,  // (36)
    float* __restrict__ out)          // (B,H,W,C) channel-last
{
    __shared__ __align__(16) char ubuf[UBUF_BYTES];   // 22.5 KB
    __shared__ float offs[TILE][NOFF];                // 9 KB
    __shared__ float msk[TILE][NMSK];                 // 4.5 KB

    __half* xh           = reinterpret_cast<__half*>(ubuf);            // [TILE][ROWA]
    float4 (*swt)[NMSK]  = reinterpret_cast<float4(*)[NMSK]>(ubuf);
    int (*sent)[NMSK]    = reinterpret_cast<int(*)[NMSK]>(ubuf + TILE * NMSK * 16);

    const int tid = threadIdx.x;
    const int blk = blockIdx.x;
    const int wt = blk % (WW / TILE);
    const int h  = (blk / (WW / TILE)) % HH;
    const int b  = blk / ((WW / TILE) * HH);
    const int w0 = wt * TILE;

    // ---- phase 0: load 32 pixels' features as fp16, PIXEL-major ----
    {
        const int px  = tid >> 3;            // 0..31
        const int c16 = (tid & 7) * 16;      // channel base
        const float4* s = reinterpret_cast<const float4*>(
            in + (((size_t)b * HH + h) * WW + (w0 + px)) * CC + c16);
        uint4 o0, o1;
        {
            const float4 f0 = s[0], f1 = s[1];
            __half2 h0 = __floats2half2_rn(f0.x, f0.y);
            __half2 h1 = __floats2half2_rn(f0.z, f0.w);
            __half2 h2 = __floats2half2_rn(f1.x, f1.y);
            __half2 h3 = __floats2half2_rn(f1.z, f1.w);
            o0.x = *reinterpret_cast<unsigned int*>(&h0);
            o0.y = *reinterpret_cast<unsigned int*>(&h1);
            o0.z = *reinterpret_cast<unsigned int*>(&h2);
            o0.w = *reinterpret_cast<unsigned int*>(&h3);
        }
        {
            const float4 f0 = s[2], f1 = s[3];
            __half2 h0 = __floats2half2_rn(f0.x, f0.y);
            __half2 h1 = __floats2half2_rn(f0.z, f0.w);
            __half2 h2 = __floats2half2_rn(f1.x, f1.y);
            __half2 h3 = __floats2half2_rn(f1.z, f1.w);
            o1.x = *reinterpret_cast<unsigned int*>(&h0);
            o1.y = *reinterpret_cast<unsigned int*>(&h1);
            o1.z = *reinterpret_cast<unsigned int*>(&h2);
            o1.w = *reinterpret_cast<unsigned int*>(&h3);
        }
        uint4* d = reinterpret_cast<uint4*>(&xh[px * ROWA + c16]);
        d[0] = o0;
        d[1] = o1;
    }
    __syncthreads();

    // ---- phase 1: tensor-core projection Y[32,112] = X[32,128] * W[128,112].
    // 8 warps: mtile = wid&1 (16 pixels), ntbase = wid>>1; nt = ntbase + 4i.
    {
        const int wid  = tid >> 5;
        const int lane = tid & 31;
        const int mtile  = wid & 1;
        const int ntbase = wid >> 1;
        const int nnt = (ntbase < 2) ? 4 : 3;   // nt=12,13 belong to ntbase 0,1

        const int mi = lane >> 3;
        const int arow  = mtile * 16 + (lane & 7) + ((mi & 1) << 3);
        const int akoff = (mi >> 1) << 3;
        const unsigned int abase = (unsigned int)__cvta_generic_to_shared(
            &xh[arow * ROWA + akoff]);

        float c[4][4];
        #pragma unroll
        for (int i = 0; i < 4; i++)
            #pragma unroll
            for (int q = 0; q < 4; q++) c[i][q] = 0.f;

        #pragma unroll
        for (int kt = 0; kt < 8; kt++) {
            unsigned int a0, a1, a2, a3;
            asm volatile(
                "ldmatrix.sync.aligned.m8n8.x4.shared.b16 {%0,%1,%2,%3}, [%4];"
                : "=r"(a0), "=r"(a1), "=r"(a2), "=r"(a3)
                : "r"(abase + kt * 16 * 2));
            #pragma unroll
            for (int i = 0; i < 4; i++) {
                if (i < nnt) {
                    const int nt = ntbase + 4 * i;
                    const uint2 bf = wfragB[(nt * 8 + kt) * 32 + lane];
                    asm volatile(
                        "mma.sync.aligned.m16n8k16.row.col.f32.f16.f16.f32 "
                        "{%0,%1,%2,%3}, {%4,%5,%6,%7}, {%8,%9}, {%0,%1,%2,%3};"
                        : "+f"(c[i][0]), "+f"(c[i][1]), "+f"(c[i][2]), "+f"(c[i][3])
                        : "r"(a0), "r"(a1), "r"(a2), "r"(a3),
                          "r"(bf.x), "r"(bf.y));
                }
            }
        }
        // store fragments to offs/msk
        const int row0 = mtile * 16 + (lane >> 2);
        const int row1 = row0 + 8;
        #pragma unroll
        for (int i = 0; i < 4; i++) {
            if (i < nnt) {
                const int nt = ntbase + 4 * i;
                const int j0 = nt * 8 + (lane & 3) * 2;
                if (j0 < NOFF) {
                    *reinterpret_cast<float2*>(&offs[row0][j0]) =
                        make_float2(c[i][0], c[i][1]);
                    *reinterpret_cast<float2*>(&offs[row1][j0]) =
                        make_float2(c[i][2], c[i][3]);
                } else if (j0 < NOFF + NMSK) {
                    const int jm = j0 - NOFF;
                    *reinterpret_cast<float2*>(&msk[row0][jm]) =
                        make_float2(c[i][0], c[i][1]);
                    *reinterpret_cast<float2*>(&msk[row1][jm]) =
                        make_float2(c[i][2], c[i][3]);
                }
            }
        }
    }
    __syncthreads();

    // ---- phase 2: softmax over the 9 taps per (pixel, group); bias folded ----
    if (tid < TILE * GG) {
        const int pp = tid / GG, g = tid % GG;
        float* m = &msk[pp][g * PP];
        const float* bm = &bmask[g * PP];
        float v[PP];
        float mx = -1e30f;
        #pragma unroll
        for (int p = 0; p < PP; p++) { v[p] = m[p] + __ldg(&bm[p]); mx = fmaxf(mx, v[p]); }
        float e[PP], s = 0.f;
        #pragma unroll
        for (int p = 0; p < PP; p++) { e[p] = __expf(v[p] - mx); s += e[p]; }
        const float inv = 1.f / s;
        #pragma unroll
        for (int p = 0; p < PP; p++) m[p] = e[p] * inv;
    }
    __syncthreads();

    // ---- phase 2.5: mask-folded corner weights + scratch entry (x8 units) ----
    for (int idx = tid; idx < TILE * NMSK; idx += NTHR) {
        const int pp = idx / NMSK;
        const int gp = idx % NMSK;
        const int g  = gp / PP;
        const int p  = gp % PP;
        const float dx = offs[pp][gp * 2 + 0] + __ldg(&boff[gp * 2 + 0]);
        const float dy = offs[pp][gp * 2 + 1] + __ldg(&boff[gp * 2 + 1]);
        const float px = (float)(w0 + pp) + (float)(p / 3) + dx;   // padded coords
        const float py = (float)h + (float)(p % 3) + dy;
        const float x0f = floorf(px), y0f = floorf(py);
        const float tx = px - x0f, ty = py - y0f;
        const int ix0 = (int)x0f, iy0 = (int)y0f;
        const float m = msk[pp][gp];

        float w00 = (1.f - tx) * (1.f - ty) * m;
        float w10 = tx * (1.f - ty) * m;
        float w01 = (1.f - tx) * ty * m;
        float w11 = tx * ty * m;
        const bool vx0 = ((unsigned)(ix0 - 1) < (unsigned)WW);
        const bool vx1 = ((unsigned)(ix0)     < (unsigned)WW);
        const bool vy0 = ((unsigned)(iy0 - 1) < (unsigned)HH);
        const bool vy1 = ((unsigned)(iy0)     < (unsigned)HH);
        if (!(vx0 && vy0)) w00 = 0.f;
        if (!(vx1 && vy0)) w10 = 0.f;
        if (!(vx0 && vy1)) w01 = 0.f;
        if (!(vx1 && vy1)) w11 = 0.f;

        swt[pp][gp] = make_float4(w00, w10, w01, w11);
        const bool ok = ((unsigned)ix0 <= 130u) && ((unsigned)iy0 <= 130u);
        sent[pp][gp] = ok ? ((((b * GG + g) * SP + iy0) * SP + ix0) * 8) : 0;
    }
    __syncthreads();

    // ---- phase 3: fp16 pair gather (proven best) ----
    const int lane = tid & 31;
    const int g3   = lane >> 3;
    const int sub  = lane & 7;
    const int cr   = sub >> 2;
    const int gp0  = g3 * PP;

    #pragma unroll
    for (int pass = 0; pass < 4; pass++) {
        const int pp = (tid >> 5) + pass * 8;
        float acc[8];
        #pragma unroll
        for (int i = 0; i < 8; i++) acc[i] = 0.f;

        #pragma unroll
        for (int p = 0; p < PP; p++) {
            const int gp = gp0 + p;
            const float4 wv = swt[pp][gp];
            const float wr0 = cr ? wv.y : wv.x;
            const float wr1 = cr ? wv.w : wv.z;
            const int e = sent[pp][gp];
            const uint4 d0 = xh_scratch[e + sub];
            const uint4 d1 = xh_scratch[e + SP8 + sub];
            float2 f;
            f = __half22float2(*reinterpret_cast<const __half2*>(&d0.x));
            acc[0] = fmaf(wr0, f.x, acc[0]); acc[1] = fmaf(wr0, f.y, acc[1]);
            f = __half22float2(*reinterpret_cast<const __half2*>(&d0.y));
            acc[2] = fmaf(wr0, f.x, acc[2]); acc[3] = fmaf(wr0, f.y, acc[3]);
            f = __half22float2(*reinterpret_cast<const __half2*>(&d0.z));
            acc[4] = fmaf(wr0, f.x, acc[4]); acc[5] = fmaf(wr0, f.y, acc[5]);
            f = __half22float2(*reinterpret_cast<const __half2*>(&d0.w));
            acc[6] = fmaf(wr0, f.x, acc[6]); acc[7] = fmaf(wr0, f.y, acc[7]);
            f = __half22float2(*reinterpret_cast<const __half2*>(&d1.x));
            acc[0] = fmaf(wr1, f.x, acc[0]); acc[1] = fmaf(wr1, f.y, acc[1]);
            f = __half22float2(*reinterpret_cast<const __half2*>(&d1.y));
            acc[2] = fmaf(wr1, f.x, acc[2]); acc[3] = fmaf(wr1, f.y, acc[3]);
            f = __half22float2(*reinterpret_cast<const __half2*>(&d1.z));
            acc[4] = fmaf(wr1, f.x, acc[4]); acc[5] = fmaf(wr1, f.y, acc[5]);
            f = __half22float2(*reinterpret_cast<const __half2*>(&d1.w));
            acc[6] = fmaf(wr1, f.x, acc[6]); acc[7] = fmaf(wr1, f.y, acc[7]);
        }
        #pragma unroll
        for (int i = 0; i < 8; i++)
            acc[i] += __shfl_xor_sync(0xFFFFFFFF, acc[i], 4);

        if (!(lane & 4)) {
            float* op = out + (((size_t)b * HH + h) * WW + (w0 + pp)) * CC
                            + g3 * 32 + sub * 8;
            *reinterpret_cast<float4*>(op) =
                make_float4(acc[0], acc[1], acc[2], acc[3]);
            *reinterpret_cast<float4*>(op + 4) =
                make_float4(acc[4], acc[5], acc[6], acc[7]);
        }
    }
}

extern "C" void kernel_launch(void* const* d_in, const int* in_sizes, int n_in,
                              void* d_out, int out_size) {
    const float* inp   = (const float*)d_in[0];
    const float* Woff  = (const float*)d_in[1];
    const float* boff  = (const float*)d_in[2];
    const float* Wmask = (const float*)d_in[3];
    const float* bmask = (const float*)d_in[4];
    float* out = (float*)d_out;

    const int conv_blocks = (NENT * 8 + 255) / 256;     // 8712
    conv_fp16<<<conv_blocks, 256>>>(inp);
    build_wfrag<<<(NFRAG + 255) / 256, 256>>>(Woff, Wmask);

    const int nblocks = BB * HH * (WW / TILE);          // 2048
    dcnv3_fused<<<nblocks, NTHR>>>(inp, boff, bmask, out);
}

// round 15
// speedup vs baseline: 2.0850x; 1.0219x over previous
#include <cuda_runtime.h>
#include <cuda_fp16.h>

// Problem constants (fixed for this dataset)
#define BB   4
#define CC   128
#define HH   128
#define WW   128
#define GG   4
#define PP   9       // K*K taps
#define NOFF 72      // G*P*2
#define NMSK 36      // G*P
#define NJ   112     // padded outputs (14 n-tiles of 8): 72 off + 36 msk + 4 pad
#define NT_TILES 14
#define TILE 32      // pixels per block
#define NTHR 256
#define ROWA 136     // xh row length in halves (128 + 8 pad; conflict-free ldmatrix)
#define SP   132     // padded scratch dim (img+pad); entry (b,g,yp,xp)
#define SP8  (SP * 8)  // row step in uint4 units

// fp16 pair-gather scratch: entry (b,g,yp,xp) = 128B =
//   [64B: ch0-31 of img col (xp-1), row (yp-1)] [64B: ch0-31 of img col xp]
#define NENT (BB * GG * SP * SP)
__device__ uint4 xh_scratch[NENT * 8];

// fragment-ordered fp16 W for mma.m16n8k16 B operand:
// wfragB[(nt*8 + kt)*32 + lane] = {half2(W[k0][j],W[k0+1][j]), half2(W[k0+8][j],W[k0+9][j])}
#define NFRAG (NT_TILES * 8 * 32)
__device__ uint2 wfragB[NFRAG];

// overlay buffer: phases 0/1 use it as xh[TILE][ROWA] fp16 (8704 B);
// phases 2.5/3 use it as swt[TILE][NMSK] float4 + sent[TILE][NMSK] int
#define UBUF_BYTES (TILE * NMSK * 16 + TILE * NMSK * 4)   // 23040

// ---------------- conversion kernel v2: no integer division ----------------
// grid: (ceil(SP/32), SP, BB*GG); block: 256 = 8 parts x 32 xp
__global__ __launch_bounds__(256) void conv_fp16(const float* __restrict__ in) {
    const int tid  = threadIdx.x;
    const int part = tid & 7;                       // 16B slice in 128B entry
    const int xp   = blockIdx.x * 32 + (tid >> 3);
    if (xp >= SP) return;
    const int yp = blockIdx.y;
    const int bg = blockIdx.z;                      // b*GG + g
    const int g  = bg & (GG - 1);
    const int b  = bg >> 2;
    const int col = xp - 1 + (part >> 2);           // part<4: left col, else right
    const int row = yp - 1;
    const int ch0 = (part & 3) * 8;
    uint4 v = make_uint4(0u, 0u, 0u, 0u);
    if ((unsigned)row < (unsigned)HH && (unsigned)col < (unsigned)WW) {
        const float4* s = reinterpret_cast<const float4*>(
            in + (((size_t)b * HH + row) * WW + col) * CC + g * 32 + ch0);
        const float4 f0 = s[0];
        const float4 f1 = s[1];
        __half2 h0 = __floats2half2_rn(f0.x, f0.y);
        __half2 h1 = __floats2half2_rn(f0.z, f0.w);
        __half2 h2 = __floats2half2_rn(f1.x, f1.y);
        __half2 h3 = __floats2half2_rn(f1.z, f1.w);
        v.x = *reinterpret_cast<unsigned int*>(&h0);
        v.y = *reinterpret_cast<unsigned int*>(&h1);
        v.z = *reinterpret_cast<unsigned int*>(&h2);
        v.w = *reinterpret_cast<unsigned int*>(&h3);
    }
    xh_scratch[((bg * SP + yp) * SP + xp) * 8 + part] = v;
}

// ---------------- W fragment builder ----------------
__device__ __forceinline__ float wall_get(const float* Woff, const float* Wmask,
                                          int k, int j) {
    if (j < NOFF) return Woff[k * NOFF + j];
    if (j < NOFF + NMSK) return Wmask[k * NMSK + (j - NOFF)];
    return 0.f;
}
__global__ __launch_bounds__(256) void build_wfrag(
    const float* __restrict__ Woff, const float* __restrict__ Wmask) {
    const int t = blockIdx.x * 256 + threadIdx.x;
    if (t >= NFRAG) return;
    const int lane = t & 31;
    const int kt   = (t >> 5) & 7;
    const int nt   = t >> 8;
    const int j  = nt * 8 + (lane >> 2);
    const int k0 = kt * 16 + (lane & 3) * 2;
    __half2 r0 = __floats2half2_rn(wall_get(Woff, Wmask, k0,     j),
                                   wall_get(Woff, Wmask, k0 + 1, j));
    __half2 r1 = __floats2half2_rn(wall_get(Woff, Wmask, k0 + 8, j),
                                   wall_get(Woff, Wmask, k0 + 9, j));
    uint2 v;
    v.x = *reinterpret_cast<unsigned int*>(&r0);
    v.y = *reinterpret_cast<unsigned int*>(&r1);
    wfragB[t] = v;
}

// ---------------- main fused kernel ----------------------------------------
__global__ __launch_bounds__(NTHR, 5) void dcnv3_fused(
    const float* __restrict__ boff,   // (72)
    const float* __restrict__ bmask,  // (36)
    float* __restrict__ out)          // (B,H,W,C) channel-last
{
    __shared__ __align__(16) char ubuf[UBUF_BYTES];   // 22.5 KB
    __shared__ float offs[TILE][NOFF];                // 9 KB
    __shared__ float msk[TILE][NMSK];                 // 4.5 KB

    __half* xh           = reinterpret_cast<__half*>(ubuf);            // [TILE][ROWA]
    float4 (*swt)[NMSK]  = reinterpret_cast<float4(*)[NMSK]>(ubuf);
    int (*sent)[NMSK]    = reinterpret_cast<int(*)[NMSK]>(ubuf + TILE * NMSK * 16);

    const int tid = threadIdx.x;
    const int blk = blockIdx.x;
    const int wt = blk % (WW / TILE);
    const int h  = (blk / (WW / TILE)) % HH;
    const int b  = blk / ((WW / TILE) * HH);
    const int w0 = wt * TILE;

    // ---- phase 0: load 32 pixels' fp16 features from the scratch (right
    // half of entry (b,g,h+1,w0+px) = img pixel (h,w0+px), group g). ----
    {
        const int px = tid >> 3;             // 0..31
        const int j  = tid & 7;              // channel-16 slot
        const int g  = j >> 1;
        const int pr = (j & 1) * 2;          // part offset within right half
        const int e8 = (((b * GG + g) * SP + (h + 1)) * SP + (w0 + px)) * 8;
        const uint4 q0 = xh_scratch[e8 + 4 + pr];
        const uint4 q1 = xh_scratch[e8 + 5 + pr];
        uint4* d = reinterpret_cast<uint4*>(&xh[px * ROWA + j * 16]);
        d[0] = q0;
        d[1] = q1;
    }
    __syncthreads();

    // ---- phase 1: tensor-core projection Y[32,112] = X[32,128] * W[128,112].
    {
        const int wid  = tid >> 5;
        const int lane = tid & 31;
        const int mtile  = wid & 1;
        const int ntbase = wid >> 1;
        const int nnt = (ntbase < 2) ? 4 : 3;   // nt=12,13 belong to ntbase 0,1

        const int mi = lane >> 3;
        const int arow  = mtile * 16 + (lane & 7) + ((mi & 1) << 3);
        const int akoff = (mi >> 1) << 3;
        const unsigned int abase = (unsigned int)__cvta_generic_to_shared(
            &xh[arow * ROWA + akoff]);

        float c[4][4];
        #pragma unroll
        for (int i = 0; i < 4; i++)
            #pragma unroll
            for (int q = 0; q < 4; q++) c[i][q] = 0.f;

        #pragma unroll
        for (int kt = 0; kt < 8; kt++) {
            unsigned int a0, a1, a2, a3;
            asm volatile(
                "ldmatrix.sync.aligned.m8n8.x4.shared.b16 {%0,%1,%2,%3}, [%4];"
                : "=r"(a0), "=r"(a1), "=r"(a2), "=r"(a3)
                : "r"(abase + kt * 16 * 2));
            #pragma unroll
            for (int i = 0; i < 4; i++) {
                if (i < nnt) {
                    const int nt = ntbase + 4 * i;
                    const uint2 bf = wfragB[(nt * 8 + kt) * 32 + lane];
                    asm volatile(
                        "mma.sync.aligned.m16n8k16.row.col.f32.f16.f16.f32 "
                        "{%0,%1,%2,%3}, {%4,%5,%6,%7}, {%8,%9}, {%0,%1,%2,%3};"
                        : "+f"(c[i][0]), "+f"(c[i][1]), "+f"(c[i][2]), "+f"(c[i][3])
                        : "r"(a0), "r"(a1), "r"(a2), "r"(a3),
                          "r"(bf.x), "r"(bf.y));
                }
            }
        }
        const int row0 = mtile * 16 + (lane >> 2);
        const int row1 = row0 + 8;
        #pragma unroll
        for (int i = 0; i < 4; i++) {
            if (i < nnt) {
                const int nt = ntbase + 4 * i;
                const int j0 = nt * 8 + (lane & 3) * 2;
                if (j0 < NOFF) {
                    *reinterpret_cast<float2*>(&offs[row0][j0]) =
                        make_float2(c[i][0], c[i][1]);
                    *reinterpret_cast<float2*>(&offs[row1][j0]) =
                        make_float2(c[i][2], c[i][3]);
                } else if (j0 < NOFF + NMSK) {
                    const int jm = j0 - NOFF;
                    *reinterpret_cast<float2*>(&msk[row0][jm]) =
                        make_float2(c[i][0], c[i][1]);
                    *reinterpret_cast<float2*>(&msk[row1][jm]) =
                        make_float2(c[i][2], c[i][3]);
                }
            }
        }
    }
    __syncthreads();

    // ---- phase 2: softmax over the 9 taps per (pixel, group); bias folded ----
    if (tid < TILE * GG) {
        const int pp = tid / GG, g = tid % GG;
        float* m = &msk[pp][g * PP];
        const float* bm = &bmask[g * PP];
        float v[PP];
        float mx = -1e30f;
        #pragma unroll
        for (int p = 0; p < PP; p++) { v[p] = m[p] + __ldg(&bm[p]); mx = fmaxf(mx, v[p]); }
        float e[PP], s = 0.f;
        #pragma unroll
        for (int p = 0; p < PP; p++) { e[p] = __expf(v[p] - mx); s += e[p]; }
        const float inv = 1.f / s;
        #pragma unroll
        for (int p = 0; p < PP; p++) m[p] = e[p] * inv;
    }
    __syncthreads();

    // ---- phase 2.5: mask-folded corner weights + scratch entry (x8 units) ----
    for (int idx = tid; idx < TILE * NMSK; idx += NTHR) {
        const int pp = idx / NMSK;
        const int gp = idx % NMSK;
        const int g  = gp / PP;
        const int p  = gp % PP;
        const float dx = offs[pp][gp * 2 + 0] + __ldg(&boff[gp * 2 + 0]);
        const float dy = offs[pp][gp * 2 + 1] + __ldg(&boff[gp * 2 + 1]);
        const float px = (float)(w0 + pp) + (float)(p / 3) + dx;   // padded coords
        const float py = (float)h + (float)(p % 3) + dy;
        const float x0f = floorf(px), y0f = floorf(py);
        const float tx = px - x0f, ty = py - y0f;
        const int ix0 = (int)x0f, iy0 = (int)y0f;
        const float m = msk[pp][gp];

        float w00 = (1.f - tx) * (1.f - ty) * m;
        float w10 = tx * (1.f - ty) * m;
        float w01 = (1.f - tx) * ty * m;
        float w11 = tx * ty * m;
        const bool vx0 = ((unsigned)(ix0 - 1) < (unsigned)WW);
        const bool vx1 = ((unsigned)(ix0)     < (unsigned)WW);
        const bool vy0 = ((unsigned)(iy0 - 1) < (unsigned)HH);
        const bool vy1 = ((unsigned)(iy0)     < (unsigned)HH);
        if (!(vx0 && vy0)) w00 = 0.f;
        if (!(vx1 && vy0)) w10 = 0.f;
        if (!(vx0 && vy1)) w01 = 0.f;
        if (!(vx1 && vy1)) w11 = 0.f;

        swt[pp][gp] = make_float4(w00, w10, w01, w11);
        const bool ok = ((unsigned)ix0 <= 130u) && ((unsigned)iy0 <= 130u);
        sent[pp][gp] = ok ? ((((b * GG + g) * SP + iy0) * SP + ix0) * 8) : 0;
    }
    __syncthreads();

    // ---- phase 3: fp16 pair gather (proven best) ----
    const int lane = tid & 31;
    const int g3   = lane >> 3;
    const int sub  = lane & 7;
    const int cr   = sub >> 2;
    const int gp0  = g3 * PP;

    #pragma unroll
    for (int pass = 0; pass < 4; pass++) {
        const int pp = (tid >> 5) + pass * 8;
        float acc[8];
        #pragma unroll
        for (int i = 0; i < 8; i++) acc[i] = 0.f;

        #pragma unroll
        for (int p = 0; p < PP; p++) {
            const int gp = gp0 + p;
            const float4 wv = swt[pp][gp];
            const float wr0 = cr ? wv.y : wv.x;
            const float wr1 = cr ? wv.w : wv.z;
            const int e = sent[pp][gp];
            const uint4 d0 = xh_scratch[e + sub];
            const uint4 d1 = xh_scratch[e + SP8 + sub];
            float2 f;
            f = __half22float2(*reinterpret_cast<const __half2*>(&d0.x));
            acc[0] = fmaf(wr0, f.x, acc[0]); acc[1] = fmaf(wr0, f.y, acc[1]);
            f = __half22float2(*reinterpret_cast<const __half2*>(&d0.y));
            acc[2] = fmaf(wr0, f.x, acc[2]); acc[3] = fmaf(wr0, f.y, acc[3]);
            f = __half22float2(*reinterpret_cast<const __half2*>(&d0.z));
            acc[4] = fmaf(wr0, f.x, acc[4]); acc[5] = fmaf(wr0, f.y, acc[5]);
            f = __half22float2(*reinterpret_cast<const __half2*>(&d0.w));
            acc[6] = fmaf(wr0, f.x, acc[6]); acc[7] = fmaf(wr0, f.y, acc[7]);
            f = __half22float2(*reinterpret_cast<const __half2*>(&d1.x));
            acc[0] = fmaf(wr1, f.x, acc[0]); acc[1] = fmaf(wr1, f.y, acc[1]);
            f = __half22float2(*reinterpret_cast<const __half2*>(&d1.y));
            acc[2] = fmaf(wr1, f.x, acc[2]); acc[3] = fmaf(wr1, f.y, acc[3]);
            f = __half22float2(*reinterpret_cast<const __half2*>(&d1.z));
            acc[4] = fmaf(wr1, f.x, acc[4]); acc[5] = fmaf(wr1, f.y, acc[5]);
            f = __half22float2(*reinterpret_cast<const __half2*>(&d1.w));
            acc[6] = fmaf(wr1, f.x, acc[6]); acc[7] = fmaf(wr1, f.y, acc[7]);
        }
        #pragma unroll
        for (int i = 0; i < 8; i++)
            acc[i] += __shfl_xor_sync(0xFFFFFFFF, acc[i], 4);

        if (!(lane & 4)) {
            float* op = out + (((size_t)b * HH + h) * WW + (w0 + pp)) * CC
                            + g3 * 32 + sub * 8;
            *reinterpret_cast<float4*>(op) =
                make_float4(acc[0], acc[1], acc[2], acc[3]);
            *reinterpret_cast<float4*>(op + 4) =
                make_float4(acc[4], acc[5], acc[6], acc[7]);
        }
    }
}

extern "C" void kernel_launch(void* const* d_in, const int* in_sizes, int n_in,
                              void* d_out, int out_size) {
    const float* inp   = (const float*)d_in[0];
    const float* Woff  = (const float*)d_in[1];
    const float* boff  = (const float*)d_in[2];
    const float* Wmask = (const float*)d_in[3];
    const float* bmask = (const float*)d_in[4];
    float* out = (float*)d_out;

    build_wfrag<<<(NFRAG + 255) / 256, 256>>>(Woff, Wmask);
    dim3 cgrid((SP + 31) / 32, SP, BB * GG);            // 5 x 132 x 16
    conv_fp16<<<cgrid, 256>>>(inp);

    const int nblocks = BB * HH * (WW / TILE);          // 2048
    dcnv3_fused<<<nblocks, NTHR>>>(boff, bmask, out);
}

// round 16
// speedup vs baseline: 2.1475x; 1.0300x over previous
#include <cuda_runtime.h>
#include <cuda_fp16.h>

// Problem constants (fixed for this dataset)
#define BB   4
#define CC   128
#define HH   128
#define WW   128
#define GG   4
#define PP   9       // K*K taps
#define NOFF 72      // G*P*2
#define NMSK 36      // G*P
#define NJ   112     // padded outputs (14 n-tiles of 8): 72 off + 36 msk + 4 pad
#define NT_TILES 14
#define TILE 32      // pixels per block
#define NTHR 256
#define ROWA 136     // xh row length in halves (128 + 8 pad; conflict-free ldmatrix)
#define SP   132     // padded scratch dim (img+pad); entry (b,g,yp,xp)
#define SP8  (SP * 8)  // row step in uint4 units

// fp16 pair-gather scratch: entry (b,g,yp,xp) = 128B =
//   [64B: ch0-31 of img col (xp-1), row (yp-1)] [64B: ch0-31 of img col xp]
#define NENT (BB * GG * SP * SP)
__device__ uint4 xh_scratch[NENT * 8];

// fragment-ordered fp16 W for mma.m16n8k16 B operand:
// wfragB[(nt*8 + kt)*32 + lane] = {half2(W[k0][j],W[k0+1][j]), half2(W[k0+8][j],W[k0+9][j])}
#define NFRAG (NT_TILES * 8 * 32)   // 3584 = 14 blocks x 256 threads
__device__ uint2 wfragB[NFRAG];

// overlay buffer: phases 0/1 use it as xh[TILE][ROWA] fp16 (8704 B);
// phases 2.5/3 use it as swt[TILE][NMSK] float4 + sent[TILE][NMSK] int
#define UBUF_BYTES (TILE * NMSK * 16 + TILE * NMSK * 4)   // 23040

__device__ __forceinline__ float wall_get(const float* Woff, const float* Wmask,
                                          int k, int j) {
    if (j < NOFF) return Woff[k * NOFF + j];
    if (j < NOFF + NMSK) return Wmask[k * NMSK + (j - NOFF)];
    return 0.f;
}

// ---------------- conversion kernel: fp16 pair scratch + wfrag build -------
// grid: (ceil(SP/32)=5, SP, BB*GG); block: 256 = 8 parts x 32 xp.
// Tail blocks (x==4) have only 32/256 active conv threads; 14 of them
// (z==0, y<14) also build the W fragments with their idle threads.
__global__ __launch_bounds__(256) void conv_fp16(
    const float* __restrict__ in,
    const float* __restrict__ Woff, const float* __restrict__ Wmask) {
    const int tid  = threadIdx.x;

    // ---- piggy-backed W fragment build on otherwise-dead tail blocks ----
    if (blockIdx.x == 4 && blockIdx.z == 0 && blockIdx.y < NT_TILES) {
        const int t = blockIdx.y * 256 + tid;      // 0..3583 == NFRAG-1
        const int lane = t & 31;
        const int kt   = (t >> 5) & 7;
        const int nt   = t >> 8;
        const int j  = nt * 8 + (lane >> 2);
        const int k0 = kt * 16 + (lane & 3) * 2;
        __half2 r0 = __floats2half2_rn(wall_get(Woff, Wmask, k0,     j),
                                       wall_get(Woff, Wmask, k0 + 1, j));
        __half2 r1 = __floats2half2_rn(wall_get(Woff, Wmask, k0 + 8, j),
                                       wall_get(Woff, Wmask, k0 + 9, j));
        uint2 v;
        v.x = *reinterpret_cast<unsigned int*>(&r0);
        v.y = *reinterpret_cast<unsigned int*>(&r1);
        wfragB[t] = v;
    }

    const int part = tid & 7;                       // 16B slice in 128B entry
    const int xp   = blockIdx.x * 32 + (tid >> 3);
    if (xp >= SP) return;
    const int yp = blockIdx.y;
    const int bg = blockIdx.z;                      // b*GG + g
    const int g  = bg & (GG - 1);
    const int b  = bg >> 2;
    const int col = xp - 1 + (part >> 2);           // part<4: left col, else right
    const int row = yp - 1;
    const int ch0 = (part & 3) * 8;
    uint4 v = make_uint4(0u, 0u, 0u, 0u);
    if ((unsigned)row < (unsigned)HH && (unsigned)col < (unsigned)WW) {
        const float4* s = reinterpret_cast<const float4*>(
            in + (((size_t)b * HH + row) * WW + col) * CC + g * 32 + ch0);
        const float4 f0 = s[0];
        const float4 f1 = s[1];
        __half2 h0 = __floats2half2_rn(f0.x, f0.y);
        __half2 h1 = __floats2half2_rn(f0.z, f0.w);
        __half2 h2 = __floats2half2_rn(f1.x, f1.y);
        __half2 h3 = __floats2half2_rn(f1.z, f1.w);
        v.x = *reinterpret_cast<unsigned int*>(&h0);
        v.y = *reinterpret_cast<unsigned int*>(&h1);
        v.z = *reinterpret_cast<unsigned int*>(&h2);
        v.w = *reinterpret_cast<unsigned int*>(&h3);
    }
    xh_scratch[((bg * SP + yp) * SP + xp) * 8 + part] = v;
}

// ---------------- main fused kernel ----------------------------------------
__global__ __launch_bounds__(NTHR, 5) void dcnv3_fused(
    const float* __restrict__ boff,   // (72)
    const float* __restrict__ bmask,  // (36)
    float* __restrict__ out)          // (B,H,W,C) channel-last
{
    __shared__ __align__(16) char ubuf[UBUF_BYTES];   // 22.5 KB
    __shared__ float offs[TILE][NOFF];                // 9 KB
    __shared__ float msk[TILE][NMSK];                 // 4.5 KB

    __half* xh           = reinterpret_cast<__half*>(ubuf);            // [TILE][ROWA]
    float4 (*swt)[NMSK]  = reinterpret_cast<float4(*)[NMSK]>(ubuf);
    int (*sent)[NMSK]    = reinterpret_cast<int(*)[NMSK]>(ubuf + TILE * NMSK * 16);

    const int tid = threadIdx.x;
    const int blk = blockIdx.x;
    const int wt = blk % (WW / TILE);
    const int h  = (blk / (WW / TILE)) % HH;
    const int b  = blk / ((WW / TILE) * HH);
    const int w0 = wt * TILE;

    // ---- phase 0: load 32 pixels' fp16 features from the scratch (right
    // half of entry (b,g,h+1,w0+px) = img pixel (h,w0+px), group g). ----
    {
        const int px = tid >> 3;             // 0..31
        const int j  = tid & 7;              // channel-16 slot
        const int g  = j >> 1;
        const int pr = (j & 1) * 2;          // part offset within right half
        const int e8 = (((b * GG + g) * SP + (h + 1)) * SP + (w0 + px)) * 8;
        const uint4 q0 = xh_scratch[e8 + 4 + pr];
        const uint4 q1 = xh_scratch[e8 + 5 + pr];
        uint4* d = reinterpret_cast<uint4*>(&xh[px * ROWA + j * 16]);
        d[0] = q0;
        d[1] = q1;
    }
    __syncthreads();

    // ---- phase 1: tensor-core projection Y[32,112] = X[32,128] * W[128,112].
    {
        const int wid  = tid >> 5;
        const int lane = tid & 31;
        const int mtile  = wid & 1;
        const int ntbase = wid >> 1;
        const int nnt = (ntbase < 2) ? 4 : 3;   // nt=12,13 belong to ntbase 0,1

        const int mi = lane >> 3;
        const int arow  = mtile * 16 + (lane & 7) + ((mi & 1) << 3);
        const int akoff = (mi >> 1) << 3;
        const unsigned int abase = (unsigned int)__cvta_generic_to_shared(
            &xh[arow * ROWA + akoff]);

        float c[4][4];
        #pragma unroll
        for (int i = 0; i < 4; i++)
            #pragma unroll
            for (int q = 0; q < 4; q++) c[i][q] = 0.f;

        #pragma unroll
        for (int kt = 0; kt < 8; kt++) {
            unsigned int a0, a1, a2, a3;
            asm volatile(
                "ldmatrix.sync.aligned.m8n8.x4.shared.b16 {%0,%1,%2,%3}, [%4];"
                : "=r"(a0), "=r"(a1), "=r"(a2), "=r"(a3)
                : "r"(abase + kt * 16 * 2));
            #pragma unroll
            for (int i = 0; i < 4; i++) {
                if (i < nnt) {
                    const int nt = ntbase + 4 * i;
                    const uint2 bf = wfragB[(nt * 8 + kt) * 32 + lane];
                    asm volatile(
                        "mma.sync.aligned.m16n8k16.row.col.f32.f16.f16.f32 "
                        "{%0,%1,%2,%3}, {%4,%5,%6,%7}, {%8,%9}, {%0,%1,%2,%3};"
                        : "+f"(c[i][0]), "+f"(c[i][1]), "+f"(c[i][2]), "+f"(c[i][3])
                        : "r"(a0), "r"(a1), "r"(a2), "r"(a3),
                          "r"(bf.x), "r"(bf.y));
                }
            }
        }
        const int row0 = mtile * 16 + (lane >> 2);
        const int row1 = row0 + 8;
        #pragma unroll
        for (int i = 0; i < 4; i++) {
            if (i < nnt) {
                const int nt = ntbase + 4 * i;
                const int j0 = nt * 8 + (lane & 3) * 2;
                if (j0 < NOFF) {
                    *reinterpret_cast<float2*>(&offs[row0][j0]) =
                        make_float2(c[i][0], c[i][1]);
                    *reinterpret_cast<float2*>(&offs[row1][j0]) =
                        make_float2(c[i][2], c[i][3]);
                } else if (j0 < NOFF + NMSK) {
                    const int jm = j0 - NOFF;
                    *reinterpret_cast<float2*>(&msk[row0][jm]) =
                        make_float2(c[i][0], c[i][1]);
                    *reinterpret_cast<float2*>(&msk[row1][jm]) =
                        make_float2(c[i][2], c[i][3]);
                }
            }
        }
    }
    __syncthreads();

    // ---- phase 2: softmax over the 9 taps per (pixel, group); bias folded ----
    if (tid < TILE * GG) {
        const int pp = tid / GG, g = tid % GG;
        float* m = &msk[pp][g * PP];
        const float* bm = &bmask[g * PP];
        float v[PP];
        float mx = -1e30f;
        #pragma unroll
        for (int p = 0; p < PP; p++) { v[p] = m[p] + __ldg(&bm[p]); mx = fmaxf(mx, v[p]); }
        float e[PP], s = 0.f;
        #pragma unroll
        for (int p = 0; p < PP; p++) { e[p] = __expf(v[p] - mx); s += e[p]; }
        const float inv = 1.f / s;
        #pragma unroll
        for (int p = 0; p < PP; p++) m[p] = e[p] * inv;
    }
    __syncthreads();

    // ---- phase 2.5: mask-folded corner weights + scratch entry (x8 units) ----
    for (int idx = tid; idx < TILE * NMSK; idx += NTHR) {
        const int pp = idx / NMSK;
        const int gp = idx % NMSK;
        const int g  = gp / PP;
        const int p  = gp % PP;
        const float dx = offs[pp][gp * 2 + 0] + __ldg(&boff[gp * 2 + 0]);
        const float dy = offs[pp][gp * 2 + 1] + __ldg(&boff[gp * 2 + 1]);
        const float px = (float)(w0 + pp) + (float)(p / 3) + dx;   // padded coords
        const float py = (float)h + (float)(p % 3) + dy;
        const float x0f = floorf(px), y0f = floorf(py);
        const float tx = px - x0f, ty = py - y0f;
        const int ix0 = (int)x0f, iy0 = (int)y0f;
        const float m = msk[pp][gp];

        float w00 = (1.f - tx) * (1.f - ty) * m;
        float w10 = tx * (1.f - ty) * m;
        float w01 = (1.f - tx) * ty * m;
        float w11 = tx * ty * m;
        const bool vx0 = ((unsigned)(ix0 - 1) < (unsigned)WW);
        const bool vx1 = ((unsigned)(ix0)     < (unsigned)WW);
        const bool vy0 = ((unsigned)(iy0 - 1) < (unsigned)HH);
        const bool vy1 = ((unsigned)(iy0)     < (unsigned)HH);
        if (!(vx0 && vy0)) w00 = 0.f;
        if (!(vx1 && vy0)) w10 = 0.f;
        if (!(vx0 && vy1)) w01 = 0.f;
        if (!(vx1 && vy1)) w11 = 0.f;

        swt[pp][gp] = make_float4(w00, w10, w01, w11);
        const bool ok = ((unsigned)ix0 <= 130u) && ((unsigned)iy0 <= 130u);
        sent[pp][gp] = ok ? ((((b * GG + g) * SP + iy0) * SP + ix0) * 8) : 0;
    }
    __syncthreads();

    // ---- phase 3: fp16 pair gather (proven best) ----
    const int lane = tid & 31;
    const int g3   = lane >> 3;
    const int sub  = lane & 7;
    const int cr   = sub >> 2;
    const int gp0  = g3 * PP;

    #pragma unroll
    for (int pass = 0; pass < 4; pass++) {
        const int pp = (tid >> 5) + pass * 8;
        float acc[8];
        #pragma unroll
        for (int i = 0; i < 8; i++) acc[i] = 0.f;

        #pragma unroll
        for (int p = 0; p < PP; p++) {
            const int gp = gp0 + p;
            const float4 wv = swt[pp][gp];
            const float wr0 = cr ? wv.y : wv.x;
            const float wr1 = cr ? wv.w : wv.z;
            const int e = sent[pp][gp];
            const uint4 d0 = xh_scratch[e + sub];
            const uint4 d1 = xh_scratch[e + SP8 + sub];
            float2 f;
            f = __half22float2(*reinterpret_cast<const __half2*>(&d0.x));
            acc[0] = fmaf(wr0, f.x, acc[0]); acc[1] = fmaf(wr0, f.y, acc[1]);
            f = __half22float2(*reinterpret_cast<const __half2*>(&d0.y));
            acc[2] = fmaf(wr0, f.x, acc[2]); acc[3] = fmaf(wr0, f.y, acc[3]);
            f = __half22float2(*reinterpret_cast<const __half2*>(&d0.z));
            acc[4] = fmaf(wr0, f.x, acc[4]); acc[5] = fmaf(wr0, f.y, acc[5]);
            f = __half22float2(*reinterpret_cast<const __half2*>(&d0.w));
            acc[6] = fmaf(wr0, f.x, acc[6]); acc[7] = fmaf(wr0, f.y, acc[7]);
            f = __half22float2(*reinterpret_cast<const __half2*>(&d1.x));
            acc[0] = fmaf(wr1, f.x, acc[0]); acc[1] = fmaf(wr1, f.y, acc[1]);
            f = __half22float2(*reinterpret_cast<const __half2*>(&d1.y));
            acc[2] = fmaf(wr1, f.x, acc[2]); acc[3] = fmaf(wr1, f.y, acc[3]);
            f = __half22float2(*reinterpret_cast<const __half2*>(&d1.z));
            acc[4] = fmaf(wr1, f.x, acc[4]); acc[5] = fmaf(wr1, f.y, acc[5]);
            f = __half22float2(*reinterpret_cast<const __half2*>(&d1.w));
            acc[6] = fmaf(wr1, f.x, acc[6]); acc[7] = fmaf(wr1, f.y, acc[7]);
        }
        #pragma unroll
        for (int i = 0; i < 8; i++)
            acc[i] += __shfl_xor_sync(0xFFFFFFFF, acc[i], 4);

        if (!(lane & 4)) {
            float* op = out + (((size_t)b * HH + h) * WW + (w0 + pp)) * CC
                            + g3 * 32 + sub * 8;
            *reinterpret_cast<float4*>(op) =
                make_float4(acc[0], acc[1], acc[2], acc[3]);
            *reinterpret_cast<float4*>(op + 4) =
                make_float4(acc[4], acc[5], acc[6], acc[7]);
        }
    }
}

extern "C" void kernel_launch(void* const* d_in, const int* in_sizes, int n_in,
                              void* d_out, int out_size) {
    const float* inp   = (const float*)d_in[0];
    const float* Woff  = (const float*)d_in[1];
    const float* boff  = (const float*)d_in[2];
    const float* Wmask = (const float*)d_in[3];
    const float* bmask = (const float*)d_in[4];
    float* out = (float*)d_out;

    dim3 cgrid((SP + 31) / 32, SP, BB * GG);            // 5 x 132 x 16
    conv_fp16<<<cgrid, 256>>>(inp, Woff, Wmask);

    const int nblocks = BB * HH * (WW / TILE);          // 2048
    dcnv3_fused<<<nblocks, NTHR>>>(boff, bmask, out);
}

// round 17
// speedup vs baseline: 2.1825x; 1.0163x over previous
#include <cuda_runtime.h>
#include <cuda_fp16.h>

// Problem constants (fixed for this dataset)
#define BB   4
#define CC   128
#define HH   128
#define WW   128
#define GG   4
#define PP   9       // K*K taps
#define NOFF 72      // G*P*2
#define NMSK 36      // G*P
#define NT_TILES 14
#define TILE 32      // pixels per block
#define NTHR 256
#define ROWA 136     // xh row length in halves (128 + 8 pad; conflict-free ldmatrix)
#define SP   132     // padded scratch dim (img+pad); entry (b,g,yp,xp)
#define SP8  (SP * 8)  // row step in uint4 units

// fp16 pair-gather scratch: entry (b,g,yp,xp) = 128B =
//   [64B: ch0-31 of img col (xp-1), row (yp-1)] [64B: ch0-31 of img col xp]
#define NENT (BB * GG * SP * SP)
__device__ uint4 xh_scratch[NENT * 8];

// fragment-ordered fp16 W for mma.m16n8k16 B operand
#define NFRAG (NT_TILES * 8 * 32)   // 3584 = 14 blocks x 256 threads
__device__ uint2 wfragB[NFRAG];

// overlay buffer: phases 0/1 use it as xh[TILE][ROWA] fp16 (8704 B);
// phases 2.5/3: swt[TILE][NMSK] uint4 (fp16 weight packs) + sent[TILE][NMSK] int
#define UBUF_BYTES (TILE * NMSK * 16 + TILE * NMSK * 4)   // 23040

__device__ __forceinline__ float wall_get(const float* Woff, const float* Wmask,
                                          int k, int j) {
    if (j < NOFF) return Woff[k * NOFF + j];
    if (j < NOFF + NMSK) return Wmask[k * NMSK + (j - NOFF)];
    return 0.f;
}

// ---------------- conversion kernel: fp16 pair scratch + wfrag build -------
// grid: (5, SP, BB*GG); block 256 = 8 parts x 32 xp. Tail blocks (x==4) have
// 32/256 active conv threads; 14 of them also build the W fragments.
__global__ __launch_bounds__(256) void conv_fp16(
    const float* __restrict__ in,
    const float* __restrict__ Woff, const float* __restrict__ Wmask) {
    const int tid  = threadIdx.x;

    if (blockIdx.x == 4 && blockIdx.z == 0 && blockIdx.y < NT_TILES) {
        const int t = blockIdx.y * 256 + tid;      // 0..NFRAG-1
        const int lane = t & 31;
        const int kt   = (t >> 5) & 7;
        const int nt   = t >> 8;
        const int j  = nt * 8 + (lane >> 2);
        const int k0 = kt * 16 + (lane & 3) * 2;
        __half2 r0 = __floats2half2_rn(wall_get(Woff, Wmask, k0,     j),
                                       wall_get(Woff, Wmask, k0 + 1, j));
        __half2 r1 = __floats2half2_rn(wall_get(Woff, Wmask, k0 + 8, j),
                                       wall_get(Woff, Wmask, k0 + 9, j));
        uint2 v;
        v.x = *reinterpret_cast<unsigned int*>(&r0);
        v.y = *reinterpret_cast<unsigned int*>(&r1);
        wfragB[t] = v;
    }

    const int part = tid & 7;                       // 16B slice in 128B entry
    const int xp   = blockIdx.x * 32 + (tid >> 3);
    if (xp >= SP) return;
    const int yp = blockIdx.y;
    const int bg = blockIdx.z;                      // b*GG + g
    const int g  = bg & (GG - 1);
    const int b  = bg >> 2;
    const int col = xp - 1 + (part >> 2);
    const int row = yp - 1;
    const int ch0 = (part & 3) * 8;
    uint4 v = make_uint4(0u, 0u, 0u, 0u);
    if ((unsigned)row < (unsigned)HH && (unsigned)col < (unsigned)WW) {
        const float4* s = reinterpret_cast<const float4*>(
            in + (((size_t)b * HH + row) * WW + col) * CC + g * 32 + ch0);
        const float4 f0 = s[0];
        const float4 f1 = s[1];
        __half2 h0 = __floats2half2_rn(f0.x, f0.y);
        __half2 h1 = __floats2half2_rn(f0.z, f0.w);
        __half2 h2 = __floats2half2_rn(f1.x, f1.y);
        __half2 h3 = __floats2half2_rn(f1.z, f1.w);
        v.x = *reinterpret_cast<unsigned int*>(&h0);
        v.y = *reinterpret_cast<unsigned int*>(&h1);
        v.z = *reinterpret_cast<unsigned int*>(&h2);
        v.w = *reinterpret_cast<unsigned int*>(&h3);
    }
    xh_scratch[((bg * SP + yp) * SP + xp) * 8 + part] = v;
}

// ---------------- main fused kernel ----------------------------------------
__global__ __launch_bounds__(NTHR, 5) void dcnv3_fused(
    const float* __restrict__ boff,   // (72)
    const float* __restrict__ bmask,  // (36)
    float* __restrict__ out)          // (B,H,W,C) channel-last
{
    __shared__ __align__(16) char ubuf[UBUF_BYTES];   // 22.5 KB
    __shared__ float offs[TILE][NOFF];                // 9 KB
    __shared__ float msk[TILE][NMSK];                 // 4.5 KB

    __half* xh          = reinterpret_cast<__half*>(ubuf);            // [TILE][ROWA]
    uint4 (*swt)[NMSK]  = reinterpret_cast<uint4(*)[NMSK]>(ubuf);     // fp16 packs
    int (*sent)[NMSK]   = reinterpret_cast<int(*)[NMSK]>(ubuf + TILE * NMSK * 16);

    const int tid = threadIdx.x;
    const int blk = blockIdx.x;
    const int wt = blk % (WW / TILE);
    const int h  = (blk / (WW / TILE)) % HH;
    const int b  = blk / ((WW / TILE) * HH);
    const int w0 = wt * TILE;

    // ---- phase 0: load 32 pixels' fp16 features from the scratch ----
    {
        const int px = tid >> 3;             // 0..31
        const int j  = tid & 7;              // channel-16 slot
        const int g  = j >> 1;
        const int pr = (j & 1) * 2;
        const int e8 = (((b * GG + g) * SP + (h + 1)) * SP + (w0 + px)) * 8;
        const uint4 q0 = xh_scratch[e8 + 4 + pr];
        const uint4 q1 = xh_scratch[e8 + 5 + pr];
        uint4* d = reinterpret_cast<uint4*>(&xh[px * ROWA + j * 16]);
        d[0] = q0;
        d[1] = q1;
    }
    __syncthreads();

    // ---- phase 1: tensor-core projection Y[32,112] = X[32,128]*W[128,112] ----
    {
        const int wid  = tid >> 5;
        const int lane = tid & 31;
        const int mtile  = wid & 1;
        const int ntbase = wid >> 1;
        const int nnt = (ntbase < 2) ? 4 : 3;

        const int mi = lane >> 3;
        const int arow  = mtile * 16 + (lane & 7) + ((mi & 1) << 3);
        const int akoff = (mi >> 1) << 3;
        const unsigned int abase = (unsigned int)__cvta_generic_to_shared(
            &xh[arow * ROWA + akoff]);

        float c[4][4];
        #pragma unroll
        for (int i = 0; i < 4; i++)
            #pragma unroll
            for (int q = 0; q < 4; q++) c[i][q] = 0.f;

        #pragma unroll
        for (int kt = 0; kt < 8; kt++) {
            unsigned int a0, a1, a2, a3;
            asm volatile(
                "ldmatrix.sync.aligned.m8n8.x4.shared.b16 {%0,%1,%2,%3}, [%4];"
                : "=r"(a0), "=r"(a1), "=r"(a2), "=r"(a3)
                : "r"(abase + kt * 16 * 2));
            #pragma unroll
            for (int i = 0; i < 4; i++) {
                if (i < nnt) {
                    const int nt = ntbase + 4 * i;
                    const uint2 bf = wfragB[(nt * 8 + kt) * 32 + lane];
                    asm volatile(
                        "mma.sync.aligned.m16n8k16.row.col.f32.f16.f16.f32 "
                        "{%0,%1,%2,%3}, {%4,%5,%6,%7}, {%8,%9}, {%0,%1,%2,%3};"
                        : "+f"(c[i][0]), "+f"(c[i][1]), "+f"(c[i][2]), "+f"(c[i][3])
                        : "r"(a0), "r"(a1), "r"(a2), "r"(a3),
                          "r"(bf.x), "r"(bf.y));
                }
            }
        }
        const int row0 = mtile * 16 + (lane >> 2);
        const int row1 = row0 + 8;
        #pragma unroll
        for (int i = 0; i < 4; i++) {
            if (i < nnt) {
                const int nt = ntbase + 4 * i;
                const int j0 = nt * 8 + (lane & 3) * 2;
                if (j0 < NOFF) {
                    *reinterpret_cast<float2*>(&offs[row0][j0]) =
                        make_float2(c[i][0], c[i][1]);
                    *reinterpret_cast<float2*>(&offs[row1][j0]) =
                        make_float2(c[i][2], c[i][3]);
                } else if (j0 < NOFF + NMSK) {
                    const int jm = j0 - NOFF;
                    *reinterpret_cast<float2*>(&msk[row0][jm]) =
                        make_float2(c[i][0], c[i][1]);
                    *reinterpret_cast<float2*>(&msk[row1][jm]) =
                        make_float2(c[i][2], c[i][3]);
                }
            }
        }
    }
    __syncthreads();

    // ---- phase 2: softmax over the 9 taps per (pixel, group); bias folded ----
    if (tid < TILE * GG) {
        const int pp = tid / GG, g = tid % GG;
        float* m = &msk[pp][g * PP];
        const float* bm = &bmask[g * PP];
        float v[PP];
        float mx = -1e30f;
        #pragma unroll
        for (int p = 0; p < PP; p++) { v[p] = m[p] + __ldg(&bm[p]); mx = fmaxf(mx, v[p]); }
        float e[PP], s = 0.f;
        #pragma unroll
        for (int p = 0; p < PP; p++) { e[p] = __expf(v[p] - mx); s += e[p]; }
        const float inv = 1.f / s;
        #pragma unroll
        for (int p = 0; p < PP; p++) m[p] = e[p] * inv;
    }
    __syncthreads();

    // ---- phase 2.5: fp16-packed corner weights + scratch entry (x8 units) ----
    // 1152 items; incremental pp/gp (256 = 7*36 + 4) avoids div/mod per iter.
    {
        int pp = tid / NMSK;
        int gp = tid - pp * NMSK;
        #pragma unroll
        for (int it = 0; it < 5; it++) {
            if (pp < TILE) {
                const int g = gp / PP;
                const int p = gp - g * PP;
                const float dx = offs[pp][gp * 2 + 0] + __ldg(&boff[gp * 2 + 0]);
                const float dy = offs[pp][gp * 2 + 1] + __ldg(&boff[gp * 2 + 1]);
                const float px = (float)(w0 + pp) + (float)(p / 3) + dx;
                const float py = (float)h + (float)(p % 3) + dy;
                const float x0f = floorf(px), y0f = floorf(py);
                const float tx = px - x0f, ty = py - y0f;
                const int ix0 = (int)x0f, iy0 = (int)y0f;
                const float m = msk[pp][gp];

                float w00 = (1.f - tx) * (1.f - ty) * m;
                float w10 = tx * (1.f - ty) * m;
                float w01 = (1.f - tx) * ty * m;
                float w11 = tx * ty * m;
                const bool vx0 = ((unsigned)(ix0 - 1) < (unsigned)WW);
                const bool vx1 = ((unsigned)(ix0)     < (unsigned)WW);
                const bool vy0 = ((unsigned)(iy0 - 1) < (unsigned)HH);
                const bool vy1 = ((unsigned)(iy0)     < (unsigned)HH);
                if (!(vx0 && vy0)) w00 = 0.f;
                if (!(vx1 && vy0)) w10 = 0.f;
                if (!(vx0 && vy1)) w01 = 0.f;
                if (!(vx1 && vy1)) w11 = 0.f;

                // pack duplicated half2 weights: {w00,w10,w01,w11}
                __half2 hw00 = __floats2half2_rn(w00, w00);
                __half2 hw10 = __floats2half2_rn(w10, w10);
                __half2 hw01 = __floats2half2_rn(w01, w01);
                __half2 hw11 = __floats2half2_rn(w11, w11);
                uint4 pk;
                pk.x = *reinterpret_cast<unsigned int*>(&hw00);
                pk.y = *reinterpret_cast<unsigned int*>(&hw10);
                pk.z = *reinterpret_cast<unsigned int*>(&hw01);
                pk.w = *reinterpret_cast<unsigned int*>(&hw11);
                swt[pp][gp] = pk;
                const bool ok = ((unsigned)ix0 <= 130u) && ((unsigned)iy0 <= 130u);
                sent[pp][gp] = ok ? ((((b * GG + g) * SP + iy0) * SP + ix0) * 8) : 0;
            }
            pp += 7; gp += 4;
            if (gp >= NMSK) { gp -= NMSK; pp += 1; }
        }
    }
    __syncthreads();

    // ---- phase 3: fp16 pair gather with packed fp16 tap-combine.
    // t = w_row0 * v_row0 + w_row1 * v_row1 in half2, then fp32 accumulate.
    const int lane = tid & 31;
    const int g3   = lane >> 3;
    const int sub  = lane & 7;
    const int cr   = sub >> 2;
    const int gp0  = g3 * PP;

    #pragma unroll
    for (int pass = 0; pass < 4; pass++) {
        const int pp = (tid >> 5) + pass * 8;
        float acc[8];
        #pragma unroll
        for (int i = 0; i < 8; i++) acc[i] = 0.f;

        #pragma unroll
        for (int p = 0; p < PP; p++) {
            const int gp = gp0 + p;
            const uint4 wp = swt[pp][gp];
            const unsigned int w0b = cr ? wp.y : wp.x;   // row-y0 weight (dup)
            const unsigned int w1b = cr ? wp.w : wp.z;   // row-y1 weight (dup)
            const __half2 w0h = *reinterpret_cast<const __half2*>(&w0b);
            const __half2 w1h = *reinterpret_cast<const __half2*>(&w1b);
            const int e = sent[pp][gp];
            const uint4 d0 = xh_scratch[e + sub];
            const uint4 d1 = xh_scratch[e + SP8 + sub];

            __half2 t;
            float2 f;
            t = __hmul2(w0h, *reinterpret_cast<const __half2*>(&d0.x));
            t = __hfma2(w1h, *reinterpret_cast<const __half2*>(&d1.x), t);
            f = __half22float2(t);
            acc[0] += f.x; acc[1] += f.y;
            t = __hmul2(w0h, *reinterpret_cast<const __half2*>(&d0.y));
            t = __hfma2(w1h, *reinterpret_cast<const __half2*>(&d1.y), t);
            f = __half22float2(t);
            acc[2] += f.x; acc[3] += f.y;
            t = __hmul2(w0h, *reinterpret_cast<const __half2*>(&d0.z));
            t = __hfma2(w1h, *reinterpret_cast<const __half2*>(&d1.z), t);
            f = __half22float2(t);
            acc[4] += f.x; acc[5] += f.y;
            t = __hmul2(w0h, *reinterpret_cast<const __half2*>(&d0.w));
            t = __hfma2(w1h, *reinterpret_cast<const __half2*>(&d1.w), t);
            f = __half22float2(t);
            acc[6] += f.x; acc[7] += f.y;
        }
        #pragma unroll
        for (int i = 0; i < 8; i++)
            acc[i] += __shfl_xor_sync(0xFFFFFFFF, acc[i], 4);

        if (!(lane & 4)) {
            float* op = out + (((size_t)b * HH + h) * WW + (w0 + pp)) * CC
                            + g3 * 32 + sub * 8;
            *reinterpret_cast<float4*>(op) =
                make_float4(acc[0], acc[1], acc[2], acc[3]);
            *reinterpret_cast<float4*>(op + 4) =
                make_float4(acc[4], acc[5], acc[6], acc[7]);
        }
    }
}

extern "C" void kernel_launch(void* const* d_in, const int* in_sizes, int n_in,
                              void* d_out, int out_size) {
    const float* inp   = (const float*)d_in[0];
    const float* Woff  = (const float*)d_in[1];
    const float* boff  = (const float*)d_in[2];
    const float* Wmask = (const float*)d_in[3];
    const float* bmask = (const float*)d_in[4];
    float* out = (float*)d_out;

    dim3 cgrid((SP + 31) / 32, SP, BB * GG);            // 5 x 132 x 16
    conv_fp16<<<cgrid, 256>>>(inp, Woff, Wmask);

    const int nblocks = BB * HH * (WW / TILE);          // 2048
    dcnv3_fused<<<nblocks, NTHR>>>(boff, bmask, out);
}